// round 3
// baseline (speedup 1.0000x reference)
#include <cuda_runtime.h>
#include <mma.h>
#include <math.h>

using namespace nvcuda;

#define EMBED 256
#define NH 8
#define NL 3
#define NP 4
#define HD 32
#define P2 8
#define B_ 4
#define NQ 300
#define NK 17
#define LQ (NQ * NK)        // 5100
#define LTOT 13125          // 100*100 + 50*50 + 25*25
#define MQ (B_ * LQ)        // 20400
#define MV (B_ * LTOT)      // 52500
#define NQK 480             // 384 offsets + 96 attn logits, fused

__constant__ int c_lvlH[NL] = {100, 50, 25};
__constant__ int c_lvlW[NL] = {100, 50, 25};
__constant__ int c_lvlS[NL] = {0, 10000, 12500};

// scratch
__device__ float g_v[B_ * NH * LTOT * HD];   // [b][h][pix][d] 53.76 MB
__device__ float g_offaw[MQ * NQK];          // [bq][480]: 384 off + 96 logits
__device__ float g_tmp[MQ * EMBED];          // sampled output pre-W_out
__device__ float g_Wc[NQK * EMBED];          // concat(W_off, W_attn)
__device__ float g_bc[NQK];                  // concat(b_off, b_attn)

// ---------------------------------------------------------------------------
// tf32 WMMA GEMM, 2-stage cp.async pipeline.
// C[M,N] = A[M,K] @ B[N,K]^T + bias[N]
// BM=128, BN=128, BK=32; 8 warps, warp tile 32x64 (2x4 m16n16k8 frags).
// MODE 0: row-major out. MODE 1: scatter to g_v layout [b][h][pix][d].
// Dynamic smem: 2 stages * (128+128)*36 floats = 73728 B (epilogue reuses it).
// ---------------------------------------------------------------------------
#define BM 128
#define BN 128
#define BK 32
#define LDS_ 36              // BK + 4 pad; row stride 144B (16B aligned)
#define STAGE_F ((BM + BN) * LDS_)   // 9216 floats per stage
#define LDC2 132             // BN + 4

__device__ __forceinline__ void cpa16(float* s, const float* g, bool pred) {
    unsigned ss = (unsigned)__cvta_generic_to_shared(s);
    int sz = pred ? 16 : 0;
    asm volatile("cp.async.cg.shared.global [%0], [%1], 16, %2;\n"
                 :: "r"(ss), "l"(g), "r"(sz));
}

template <int MODE>
__global__ void __launch_bounds__(256)
gemm_wmma(const float* __restrict__ A, const float* __restrict__ Bm,
          const float* __restrict__ bias, float* __restrict__ C,
          int M, int N, int K) {
    extern __shared__ float smem[];

    int tid = threadIdx.x;
    int warp = tid >> 5;
    int wr = warp >> 1;          // 0..3  -> rows 32*wr
    int wc = warp & 1;           // 0..1  -> cols 64*wc
    int bm = blockIdx.y * BM, bn = blockIdx.x * BN;

    int r  = tid >> 3;           // 0..31
    int c4 = (tid & 7) * 4;      // 0..28

    wmma::fragment<wmma::accumulator, 16, 16, 8, float> acc[2][4];
#pragma unroll
    for (int i = 0; i < 2; i++)
#pragma unroll
        for (int j = 0; j < 4; j++) wmma::fill_fragment(acc[i][j], 0.f);

    int niter = K / BK;

    // stage loader
    auto load_stage = [&](int s, int k0) {
        float* sa = smem + s * STAGE_F;
        float* sb = sa + BM * LDS_;
#pragma unroll
        for (int i = 0; i < 4; i++) {
            int row = r + 32 * i;
            int gr = bm + row;
            bool p = gr < M;
            cpa16(&sa[row * LDS_ + c4], &A[(size_t)(p ? gr : 0) * K + k0 + c4], p);
        }
#pragma unroll
        for (int i = 0; i < 4; i++) {
            int row = r + 32 * i;
            int gc = bn + row;
            bool p = gc < N;
            cpa16(&sb[row * LDS_ + c4], &Bm[(size_t)(p ? gc : 0) * K + k0 + c4], p);
        }
        asm volatile("cp.async.commit_group;\n");
    };

    load_stage(0, 0);

    for (int it = 0; it < niter; it++) {
        asm volatile("cp.async.wait_group 0;\n");
        __syncthreads();
        if (it + 1 < niter) load_stage((it + 1) & 1, (it + 1) * BK);

        float* sa = smem + (it & 1) * STAGE_F;
        float* sb = sa + BM * LDS_;
#pragma unroll
        for (int ks = 0; ks < BK; ks += 8) {
            wmma::fragment<wmma::matrix_a, 16, 16, 8, wmma::precision::tf32, wmma::row_major> af[2];
            wmma::fragment<wmma::matrix_b, 16, 16, 8, wmma::precision::tf32, wmma::col_major> bf[4];
#pragma unroll
            for (int i = 0; i < 2; i++) {
                wmma::load_matrix_sync(af[i], &sa[(wr * 32 + i * 16) * LDS_ + ks], LDS_);
#pragma unroll
                for (int t = 0; t < af[i].num_elements; t++)
                    af[i].x[t] = wmma::__float_to_tf32(af[i].x[t]);
            }
#pragma unroll
            for (int j = 0; j < 4; j++) {
                wmma::load_matrix_sync(bf[j], &sb[(wc * 64 + j * 16) * LDS_ + ks], LDS_);
#pragma unroll
                for (int t = 0; t < bf[j].num_elements; t++)
                    bf[j].x[t] = wmma::__float_to_tf32(bf[j].x[t]);
            }
#pragma unroll
            for (int i = 0; i < 2; i++)
#pragma unroll
                for (int j = 0; j < 4; j++)
                    wmma::mma_sync(acc[i][j], af[i], bf[j], acc[i][j]);
        }
        __syncthreads();
    }

    // epilogue: park accumulators in smem (reuse), then bias + store
    float* Cs = smem;
#pragma unroll
    for (int i = 0; i < 2; i++)
#pragma unroll
        for (int j = 0; j < 4; j++)
            wmma::store_matrix_sync(&Cs[(wr * 32 + i * 16) * LDC2 + wc * 64 + j * 16],
                                    acc[i][j], LDC2, wmma::mem_row_major);
    __syncthreads();

    for (int i = tid; i < (BM * BN) / 4; i += 256) {
        int row = i >> 5;             // / (BN/4)
        int c0 = (i & 31) * 4;
        int gr = bm + row, gc = bn + c0;
        if (gr < M && gc < N) {       // N is a multiple of 4
            float4 v = *reinterpret_cast<float4*>(&Cs[row * LDC2 + c0]);
            float4 bb = *reinterpret_cast<const float4*>(&bias[gc]);
            v.x += bb.x; v.y += bb.y; v.z += bb.z; v.w += bb.w;
            if (MODE == 0) {
                *reinterpret_cast<float4*>(&C[(size_t)gr * N + gc]) = v;
            } else {
                int b = gr / LTOT, l = gr % LTOT;
                int h = gc >> 5, d = gc & 31;
                *reinterpret_cast<float4*>(
                    &C[(((size_t)(b * NH + h)) * LTOT + l) * HD + d]) = v;
            }
        }
    }
}

// ---------------------------------------------------------------------------
// Bilinear sampling + fused softmax + attention-weighted accumulation.
// One block per (b,q); one warp per head; lane = channel d.
// offaw row: [0..383] offsets (h*48 + (l*4+p)*4 + comp), [384..479] logits.
// ---------------------------------------------------------------------------
__global__ void __launch_bounds__(NH * 32)
sample_kernel(const float* __restrict__ ref_l, const float* __restrict__ ref_r,
              const float* __restrict__ offaw, float* __restrict__ out) {
    int bq = blockIdx.x;
    int b = bq / LQ, q = bq % LQ;
    int h = threadIdx.x >> 5;
    int d = threadIdx.x & 31;
    int nqi = q / NK, nki = q % NK;

    const float* rowp = offaw + (size_t)bq * NQK;
    const float* offp = rowp + h * (NL * NP * 4);
    const float* logp = rowp + 384 + h * (NL * NP);
    const float* vb   = g_v + ((size_t)(b * NH + h)) * LTOT * HD + d;

    // per-warp softmax over 12 logits (every lane computes it; broadcast loads)
    float wsm[12];
    {
        float m = -1e30f;
#pragma unroll
        for (int i = 0; i < 12; i++) { wsm[i] = __ldg(&logp[i]); m = fmaxf(m, wsm[i]); }
        float s = 0.f;
#pragma unroll
        for (int i = 0; i < 12; i++) { wsm[i] = __expf(wsm[i] - m); s += wsm[i]; }
        float inv = 1.f / s;
#pragma unroll
        for (int i = 0; i < 12; i++) wsm[i] *= inv;
    }

    float acc = 0.f;
#pragma unroll
    for (int l = 0; l < NL; l++) {
        int H = c_lvlH[l], W = c_lvlW[l];
        const float* vlev = vb + (size_t)c_lvlS[l] * HD;
        float fW = (float)W, fH = (float)H;
        size_t rbase = ((((size_t)b * NQ + nqi) * NL + l) * NK + nki) * 2;
        float rlx = __ldg(&ref_l[rbase]);
        float rly = __ldg(&ref_l[rbase + 1]);
        float rrx = __ldg(&ref_r[rbase]);
        float rry = __ldg(&ref_r[rbase + 1]);
#pragma unroll
        for (int p = 0; p < P2; p++) {
            int pp = p & 3;
            int sbase = (l * NP + pp) * 4 + ((p < NP) ? 0 : 2);
            float ox = __ldg(&offp[sbase]);
            float oy = __ldg(&offp[sbase + 1]);
            float w  = wsm[l * NP + pp];
            float lx = ((p < NP) ? rlx : rrx) + ox / fW;
            float ly = ((p < NP) ? rly : rry) + oy / fH;
            float x = lx * fW - 0.5f;
            float y = ly * fH - 0.5f;
            float x0f = floorf(x), y0f = floorf(y);
            int x0 = (int)x0f, y0 = (int)y0f;
            float tx = x - x0f, ty = y - y0f;
            float sval = 0.f;
#pragma unroll
            for (int dy = 0; dy < 2; dy++) {
#pragma unroll
                for (int dx = 0; dx < 2; dx++) {
                    int xi = x0 + dx, yi = y0 + dy;
                    if (xi >= 0 && xi < W && yi >= 0 && yi < H) {
                        float wt = (dx ? tx : 1.f - tx) * (dy ? ty : 1.f - ty);
                        sval += wt * __ldg(&vlev[((size_t)yi * W + xi) * HD]);
                    }
                }
            }
            acc += w * sval;
        }
    }
    out[(size_t)bq * EMBED + h * HD + d] = acc;
}

#define GEMM_SMEM (2 * STAGE_F * 4)   // 73728 bytes

extern "C" void kernel_launch(void* const* d_in, const int* in_sizes, int n_in,
                              void* d_out, int out_size) {
    const float* query = (const float*)d_in[0];
    const float* ref_l = (const float*)d_in[1];
    const float* ref_r = (const float*)d_in[2];
    const float* value = (const float*)d_in[3];
    const float* W_off  = (const float*)d_in[6];
    const float* b_off  = (const float*)d_in[7];
    const float* W_attn = (const float*)d_in[8];
    const float* b_attn = (const float*)d_in[9];
    const float* W_val  = (const float*)d_in[10];
    const float* b_val  = (const float*)d_in[11];
    const float* W_out  = (const float*)d_in[12];
    const float* b_out  = (const float*)d_in[13];
    float* out = (float*)d_out;

    float *gv, *goffaw, *gtmp, *gWc, *gbc;
    cudaGetSymbolAddress((void**)&gv, g_v);
    cudaGetSymbolAddress((void**)&goffaw, g_offaw);
    cudaGetSymbolAddress((void**)&gtmp, g_tmp);
    cudaGetSymbolAddress((void**)&gWc, g_Wc);
    cudaGetSymbolAddress((void**)&gbc, g_bc);

    cudaFuncSetAttribute(gemm_wmma<0>, cudaFuncAttributeMaxDynamicSharedMemorySize, GEMM_SMEM);
    cudaFuncSetAttribute(gemm_wmma<1>, cudaFuncAttributeMaxDynamicSharedMemorySize, GEMM_SMEM);

    // concat weights/biases for fused offset+attn GEMM
    cudaMemcpyAsync(gWc, W_off, 384 * EMBED * sizeof(float), cudaMemcpyDeviceToDevice);
    cudaMemcpyAsync(gWc + 384 * EMBED, W_attn, 96 * EMBED * sizeof(float), cudaMemcpyDeviceToDevice);
    cudaMemcpyAsync(gbc, b_off, 384 * sizeof(float), cudaMemcpyDeviceToDevice);
    cudaMemcpyAsync(gbc + 384, b_attn, 96 * sizeof(float), cudaMemcpyDeviceToDevice);

    // 1. value projection: [MV,512] @ W_val[256,512]^T -> g_v scatter
    {
        dim3 grid((EMBED + BN - 1) / BN, (MV + BM - 1) / BM);
        gemm_wmma<1><<<grid, 256, GEMM_SMEM>>>(value, W_val, b_val, gv, MV, EMBED, EMBED * 2);
    }
    // 2. fused offsets+logits: [MQ,256] @ Wc[480,256]^T
    {
        dim3 grid((NQK + BN - 1) / BN, (MQ + BM - 1) / BM);
        gemm_wmma<0><<<grid, 256, GEMM_SMEM>>>(query, gWc, gbc, goffaw, MQ, NQK, EMBED);
    }
    // 3. deformable sampling (+fused softmax)
    sample_kernel<<<MQ, NH * 32>>>(ref_l, ref_r, goffaw, gtmp);
    // 4. output projection: [MQ,256] @ W_out[256,256]^T -> d_out
    {
        dim3 grid((EMBED + BN - 1) / BN, (MQ + BM - 1) / BM);
        gemm_wmma<0><<<grid, 256, GEMM_SMEM>>>(gtmp, W_out, b_out, out, MQ, EMBED, EMBED);
    }
}

// round 4
// speedup vs baseline: 1.1411x; 1.1411x over previous
#include <cuda_runtime.h>
#include <mma.h>
#include <math.h>

using namespace nvcuda;

#define EMBED 256
#define NH 8
#define NL 3
#define NP 4
#define HD 32
#define P2 8
#define B_ 4
#define NQ 300
#define NK 17
#define LQ (NQ * NK)        // 5100
#define LTOT 13125          // 100*100 + 50*50 + 25*25
#define MQ (B_ * LQ)        // 20400
#define MV (B_ * LTOT)      // 52500
#define NQK 480             // 384 offsets + 96 attn logits, fused

__constant__ int c_lvlH[NL] = {100, 50, 25};
__constant__ int c_lvlW[NL] = {100, 50, 25};
__constant__ int c_lvlS[NL] = {0, 10000, 12500};

// scratch
__device__ float g_v[B_ * NH * LTOT * HD];   // [b][h][pix][d] 53.76 MB
__device__ float g_offaw[MQ * NQK];          // [bq][480]: 384 off + 96 logits
__device__ float g_tmp[MQ * EMBED];          // sampled output pre-W_out
__device__ float g_Wc[NQK * EMBED];          // concat(W_off, W_attn)
__device__ float g_bc[NQK];                  // concat(b_off, b_attn)

// ---------------------------------------------------------------------------
// tf32 WMMA GEMM, 2-stage cp.async pipeline, occupancy-tuned.
// C[M,N] = A[M,K] @ B[N,K]^T + bias[N]
// BM=128, BN=64, BK=32; 8 warps (4x2), warp tile 32x32 (2x2 m16n16k8 frags).
// MODE 0: row-major out. MODE 1: scatter to g_v layout [b][h][pix][d].
// smem: 2 * (128+64)*36 floats = 55296 B; epilogue reuses (128*68*4=34816 B).
// ---------------------------------------------------------------------------
#define BM 128
#define BN 64
#define BK 32
#define LDS_ 36                      // BK + 4 pad (144B row stride, 16B aligned)
#define STAGE_F ((BM + BN) * LDS_)   // 6912 floats per stage
#define LDC2 68                      // BN + 4

__device__ __forceinline__ void cpa16(float* s, const float* g, bool pred) {
    unsigned ss = (unsigned)__cvta_generic_to_shared(s);
    int sz = pred ? 16 : 0;
    asm volatile("cp.async.cg.shared.global [%0], [%1], 16, %2;\n"
                 :: "r"(ss), "l"(g), "r"(sz));
}

template <int MODE>
__global__ void __launch_bounds__(256, 2)
gemm_wmma(const float* __restrict__ A, const float* __restrict__ Bm,
          const float* __restrict__ bias, float* __restrict__ C,
          int M, int N, int K) {
    extern __shared__ float smem[];

    int tid = threadIdx.x;
    int warp = tid >> 5;
    int wr = warp >> 1;          // 0..3 -> row base 32*wr
    int wc = warp & 1;           // 0..1 -> col base 32*wc
    int bm = blockIdx.y * BM, bn = blockIdx.x * BN;

    int r  = tid >> 3;           // 0..31
    int c4 = (tid & 7) * 4;      // 0..28

    wmma::fragment<wmma::accumulator, 16, 16, 8, float> acc[2][2];
#pragma unroll
    for (int i = 0; i < 2; i++)
#pragma unroll
        for (int j = 0; j < 2; j++) wmma::fill_fragment(acc[i][j], 0.f);

    int niter = K / BK;

    auto load_stage = [&](int s, int k0) {
        float* sa = smem + s * STAGE_F;
        float* sb = sa + BM * LDS_;
#pragma unroll
        for (int i = 0; i < 4; i++) {
            int row = r + 32 * i;
            int gr = bm + row;
            bool p = gr < M;
            cpa16(&sa[row * LDS_ + c4], &A[(size_t)(p ? gr : 0) * K + k0 + c4], p);
        }
#pragma unroll
        for (int i = 0; i < 2; i++) {
            int row = r + 32 * i;
            int gc = bn + row;
            bool p = gc < N;
            cpa16(&sb[row * LDS_ + c4], &Bm[(size_t)(p ? gc : 0) * K + k0 + c4], p);
        }
        asm volatile("cp.async.commit_group;\n");
    };

    load_stage(0, 0);

    for (int it = 0; it < niter; it++) {
        asm volatile("cp.async.wait_group 0;\n");
        __syncthreads();
        if (it + 1 < niter) load_stage((it + 1) & 1, (it + 1) * BK);

        float* sa = smem + (it & 1) * STAGE_F;
        float* sb = sa + BM * LDS_;
#pragma unroll
        for (int ks = 0; ks < BK; ks += 8) {
            wmma::fragment<wmma::matrix_a, 16, 16, 8, wmma::precision::tf32, wmma::row_major> af[2];
            wmma::fragment<wmma::matrix_b, 16, 16, 8, wmma::precision::tf32, wmma::col_major> bf[2];
#pragma unroll
            for (int i = 0; i < 2; i++) {
                wmma::load_matrix_sync(af[i], &sa[(wr * 32 + i * 16) * LDS_ + ks], LDS_);
#pragma unroll
                for (int t = 0; t < af[i].num_elements; t++)
                    af[i].x[t] = wmma::__float_to_tf32(af[i].x[t]);
            }
#pragma unroll
            for (int j = 0; j < 2; j++) {
                wmma::load_matrix_sync(bf[j], &sb[(wc * 32 + j * 16) * LDS_ + ks], LDS_);
#pragma unroll
                for (int t = 0; t < bf[j].num_elements; t++)
                    bf[j].x[t] = wmma::__float_to_tf32(bf[j].x[t]);
            }
#pragma unroll
            for (int i = 0; i < 2; i++)
#pragma unroll
                for (int j = 0; j < 2; j++)
                    wmma::mma_sync(acc[i][j], af[i], bf[j], acc[i][j]);
        }
        __syncthreads();
    }

    // epilogue: park accumulators in smem (reuse), then bias + store
    float* Cs = smem;
#pragma unroll
    for (int i = 0; i < 2; i++)
#pragma unroll
        for (int j = 0; j < 2; j++)
            wmma::store_matrix_sync(&Cs[(wr * 32 + i * 16) * LDC2 + wc * 32 + j * 16],
                                    acc[i][j], LDC2, wmma::mem_row_major);
    __syncthreads();

    for (int i = tid; i < (BM * BN) / 4; i += 256) {
        int row = i >> 4;            // / (BN/4)
        int c0 = (i & 15) * 4;
        int gr = bm + row, gc = bn + c0;
        if (gr < M && gc < N) {      // N multiple of 4
            float4 v = *reinterpret_cast<float4*>(&Cs[row * LDC2 + c0]);
            float4 bb = *reinterpret_cast<const float4*>(&bias[gc]);
            v.x += bb.x; v.y += bb.y; v.z += bb.z; v.w += bb.w;
            if (MODE == 0) {
                *reinterpret_cast<float4*>(&C[(size_t)gr * N + gc]) = v;
            } else {
                int b = gr / LTOT, l = gr % LTOT;
                int h = gc >> 5, d = gc & 31;
                *reinterpret_cast<float4*>(
                    &C[(((size_t)(b * NH + h)) * LTOT + l) * HD + d]) = v;
            }
        }
    }
}

// ---------------------------------------------------------------------------
// Bilinear sampling + fused softmax + attention-weighted accumulation.
// One block per (b,q); one warp per head; lane = channel d.
// ---------------------------------------------------------------------------
__global__ void __launch_bounds__(NH * 32)
sample_kernel(const float* __restrict__ ref_l, const float* __restrict__ ref_r,
              const float* __restrict__ offaw, float* __restrict__ out) {
    int bq = blockIdx.x;
    int b = bq / LQ, q = bq % LQ;
    int h = threadIdx.x >> 5;
    int d = threadIdx.x & 31;
    int nqi = q / NK, nki = q % NK;

    const float* rowp = offaw + (size_t)bq * NQK;
    const float* offp = rowp + h * (NL * NP * 4);
    const float* logp = rowp + 384 + h * (NL * NP);
    const float* vb   = g_v + ((size_t)(b * NH + h)) * LTOT * HD + d;

    // per-warp softmax over 12 logits
    float wsm[12];
    {
        float m = -1e30f;
#pragma unroll
        for (int i = 0; i < 12; i++) { wsm[i] = __ldg(&logp[i]); m = fmaxf(m, wsm[i]); }
        float s = 0.f;
#pragma unroll
        for (int i = 0; i < 12; i++) { wsm[i] = __expf(wsm[i] - m); s += wsm[i]; }
        float inv = 1.f / s;
#pragma unroll
        for (int i = 0; i < 12; i++) wsm[i] *= inv;
    }

    float acc = 0.f;
#pragma unroll
    for (int l = 0; l < NL; l++) {
        int H = c_lvlH[l], W = c_lvlW[l];
        const float* vlev = vb + (size_t)c_lvlS[l] * HD;
        float fW = (float)W, fH = (float)H;
        size_t rbase = ((((size_t)b * NQ + nqi) * NL + l) * NK + nki) * 2;
        float rlx = __ldg(&ref_l[rbase]);
        float rly = __ldg(&ref_l[rbase + 1]);
        float rrx = __ldg(&ref_r[rbase]);
        float rry = __ldg(&ref_r[rbase + 1]);
#pragma unroll
        for (int p = 0; p < P2; p++) {
            int pp = p & 3;
            int sbase = (l * NP + pp) * 4 + ((p < NP) ? 0 : 2);
            float ox = __ldg(&offp[sbase]);
            float oy = __ldg(&offp[sbase + 1]);
            float w  = wsm[l * NP + pp];
            float lx = ((p < NP) ? rlx : rrx) + ox / fW;
            float ly = ((p < NP) ? rly : rry) + oy / fH;
            float x = lx * fW - 0.5f;
            float y = ly * fH - 0.5f;
            float x0f = floorf(x), y0f = floorf(y);
            int x0 = (int)x0f, y0 = (int)y0f;
            float tx = x - x0f, ty = y - y0f;
            float sval = 0.f;
#pragma unroll
            for (int dy = 0; dy < 2; dy++) {
#pragma unroll
                for (int dx = 0; dx < 2; dx++) {
                    int xi = x0 + dx, yi = y0 + dy;
                    if (xi >= 0 && xi < W && yi >= 0 && yi < H) {
                        float wt = (dx ? tx : 1.f - tx) * (dy ? ty : 1.f - ty);
                        sval += wt * __ldg(&vlev[((size_t)yi * W + xi) * HD]);
                    }
                }
            }
            acc += w * sval;
        }
    }
    out[(size_t)bq * EMBED + h * HD + d] = acc;
}

#define GEMM_SMEM (2 * STAGE_F * 4)   // 55296 bytes

extern "C" void kernel_launch(void* const* d_in, const int* in_sizes, int n_in,
                              void* d_out, int out_size) {
    const float* query = (const float*)d_in[0];
    const float* ref_l = (const float*)d_in[1];
    const float* ref_r = (const float*)d_in[2];
    const float* value = (const float*)d_in[3];
    const float* W_off  = (const float*)d_in[6];
    const float* b_off  = (const float*)d_in[7];
    const float* W_attn = (const float*)d_in[8];
    const float* b_attn = (const float*)d_in[9];
    const float* W_val  = (const float*)d_in[10];
    const float* b_val  = (const float*)d_in[11];
    const float* W_out  = (const float*)d_in[12];
    const float* b_out  = (const float*)d_in[13];
    float* out = (float*)d_out;

    float *gv, *goffaw, *gtmp, *gWc, *gbc;
    cudaGetSymbolAddress((void**)&gv, g_v);
    cudaGetSymbolAddress((void**)&goffaw, g_offaw);
    cudaGetSymbolAddress((void**)&gtmp, g_tmp);
    cudaGetSymbolAddress((void**)&gWc, g_Wc);
    cudaGetSymbolAddress((void**)&gbc, g_bc);

    cudaFuncSetAttribute(gemm_wmma<0>, cudaFuncAttributeMaxDynamicSharedMemorySize, GEMM_SMEM);
    cudaFuncSetAttribute(gemm_wmma<1>, cudaFuncAttributeMaxDynamicSharedMemorySize, GEMM_SMEM);

    // concat weights/biases for fused offset+attn GEMM
    cudaMemcpyAsync(gWc, W_off, 384 * EMBED * sizeof(float), cudaMemcpyDeviceToDevice);
    cudaMemcpyAsync(gWc + 384 * EMBED, W_attn, 96 * EMBED * sizeof(float), cudaMemcpyDeviceToDevice);
    cudaMemcpyAsync(gbc, b_off, 384 * sizeof(float), cudaMemcpyDeviceToDevice);
    cudaMemcpyAsync(gbc + 384, b_attn, 96 * sizeof(float), cudaMemcpyDeviceToDevice);

    // 1. value projection: [MV,512] @ W_val[256,512]^T -> g_v scatter
    {
        dim3 grid((EMBED + BN - 1) / BN, (MV + BM - 1) / BM);
        gemm_wmma<1><<<grid, 256, GEMM_SMEM>>>(value, W_val, b_val, gv, MV, EMBED, EMBED * 2);
    }
    // 2. fused offsets+logits: [MQ,256] @ Wc[480,256]^T
    {
        dim3 grid((NQK + BN - 1) / BN, (MQ + BM - 1) / BM);
        gemm_wmma<0><<<grid, 256, GEMM_SMEM>>>(query, gWc, gbc, goffaw, MQ, NQK, EMBED);
    }
    // 3. deformable sampling (+fused softmax)
    sample_kernel<<<MQ, NH * 32>>>(ref_l, ref_r, goffaw, gtmp);
    // 4. output projection: [MQ,256] @ W_out[256,256]^T -> d_out
    {
        dim3 grid((EMBED + BN - 1) / BN, (MQ + BM - 1) / BM);
        gemm_wmma<0><<<grid, 256, GEMM_SMEM>>>(gtmp, W_out, b_out, out, MQ, EMBED, EMBED);
    }
}

// round 6
// speedup vs baseline: 1.4741x; 1.2918x over previous
#include <cuda_runtime.h>
#include <cstdint>
#include <math.h>

#define EMBED 256
#define NH 8
#define NL 3
#define NP 4
#define HD 32
#define P2 8
#define B_ 4
#define NQ 300
#define NK 17
#define LQ (NQ * NK)        // 5100
#define LTOT 13125
#define MQ (B_ * LQ)        // 20400
#define MV (B_ * LTOT)      // 52500
#define NQK 480

__constant__ int c_lvlH[NL] = {100, 50, 25};
__constant__ int c_lvlW[NL] = {100, 50, 25};
__constant__ int c_lvlS[NL] = {0, 10000, 12500};

__device__ float g_v[B_ * NH * LTOT * HD];   // [b][h][pix][d]
__device__ float g_offaw[MQ * NQK];
__device__ float g_tmp[MQ * EMBED];
__device__ float g_Wc[NQK * EMBED];          // pre-rounded concat(W_off, W_attn)
__device__ float g_bc[NQK];
__device__ float g_Wvr[EMBED * 2 * EMBED];   // pre-rounded W_val (256x512)
__device__ float g_Wor[EMBED * EMBED];       // pre-rounded W_out

__device__ __forceinline__ float tf32_rna(float x) {
    uint32_t u;
    asm("cvt.rna.tf32.f32 %0, %1;" : "=r"(u) : "f"(x));
    return __uint_as_float(u);
}

__device__ __forceinline__ void cpa16_s(uint32_t s, const float* g, bool pred) {
    int sz = pred ? 16 : 0;
    asm volatile("cp.async.cg.shared.global [%0], [%1], 16, %2;\n" :: "r"(s), "l"(g), "r"(sz));
}

__device__ __forceinline__ void ldm4(uint32_t r[4], uint32_t addr) {
    asm volatile("ldmatrix.sync.aligned.m8n8.x4.shared.b16 {%0,%1,%2,%3}, [%4];"
                 : "=r"(r[0]), "=r"(r[1]), "=r"(r[2]), "=r"(r[3]) : "r"(addr));
}

__device__ __forceinline__ void mma8(float c[4], const uint32_t a[4], uint32_t b0, uint32_t b1) {
    asm volatile("mma.sync.aligned.m16n8k8.row.col.f32.tf32.tf32.f32 "
                 "{%0,%1,%2,%3}, {%4,%5,%6,%7}, {%8,%9}, {%0,%1,%2,%3};"
                 : "+f"(c[0]), "+f"(c[1]), "+f"(c[2]), "+f"(c[3])
                 : "r"(a[0]), "r"(a[1]), "r"(a[2]), "r"(a[3]), "r"(b0), "r"(b1));
}

// ---------------------------------------------------------------------------
// tf32 mma.sync GEMM: C[M,N] = A[M,K] @ B[N,K]^T + bias[N]
// BM=128, BN=64, BK=32; 8 warps (4x2); warp tile 32x32 (m16n8k8, 2m x 4n x 4k).
// 3-stage cp.async ring, padded smem (LDS_=36 floats -> conflict-free ldmatrix).
// B (weights) pre-rounded to tf32. CVTA: round A fragments in-register.
// MODE 0: row-major out. MODE 1: scatter to g_v layout [b][h][pix][d].
// ---------------------------------------------------------------------------
#define BM 128
#define BN 64
#define BK 32
#define LDS_ 36
#define STAGE_B ((BM + BN) * LDS_ * 4)   // 27648 bytes
#define A_B (BM * LDS_ * 4)              // 18432
#define GEMM_SMEM (3 * STAGE_B)          // 82944

__device__ __forceinline__ void load_stage(
    const float* __restrict__ A, const float* __restrict__ Bm,
    uint32_t sa, uint32_t sb, int bm, int bn, int M, int N, int K, int k0, int tid) {
#pragma unroll
    for (int jj = 0; jj < 4; jj++) {       // A: 128 rows x 8 x float4
        int c = tid + 256 * jj;
        int row = c >> 3, kq = c & 7;
        int gr = bm + row;
        bool p = gr < M;
        cpa16_s(sa + (row * LDS_ + kq * 4) * 4, &A[(size_t)(p ? gr : 0) * K + k0 + kq * 4], p);
    }
#pragma unroll
    for (int jj = 0; jj < 2; jj++) {       // B: 64 rows x 8 x float4
        int c = tid + 256 * jj;
        int row = c >> 3, kq = c & 7;
        int gc = bn + row;
        bool p = gc < N;
        cpa16_s(sb + (row * LDS_ + kq * 4) * 4, &Bm[(size_t)(p ? gc : 0) * K + k0 + kq * 4], p);
    }
    asm volatile("cp.async.commit_group;\n");
}

template <int MODE, int CVTA>
__global__ void __launch_bounds__(256, 2)
gemm_mma(const float* __restrict__ A, const float* __restrict__ Bm,
         const float* __restrict__ bias, float* __restrict__ C,
         int M, int N, int K) {
    extern __shared__ char smem[];
    uint32_t sbase;
    asm("{ .reg .u64 t; cvta.to.shared.u64 t, %1; cvt.u32.u64 %0, t; }"
        : "=r"(sbase) : "l"(smem));

    int tid = threadIdx.x;
    int warp = tid >> 5, lane = tid & 31;
    int wr = warp >> 1, wc = warp & 1;
    int bm = blockIdx.y * BM, bn = blockIdx.x * BN;

    // ldmatrix lane-derived offsets
    int j8 = lane >> 3, rr = lane & 7;
    int aoff = (wr * 32 + rr + ((j8 & 1) << 3)) * LDS_ + ((j8 >> 1) << 2);
    int boff = (wc * 32 + rr + ((j8 >> 1) << 3)) * LDS_ + ((j8 & 1) << 2);

    float acc[2][4][4];
#pragma unroll
    for (int i = 0; i < 2; i++)
#pragma unroll
        for (int n = 0; n < 4; n++)
#pragma unroll
            for (int t = 0; t < 4; t++) acc[i][n][t] = 0.f;

    int niter = K / BK;
#pragma unroll
    for (int s = 0; s < 3; s++) {
        uint32_t sa = sbase + s * STAGE_B;
        load_stage(A, Bm, sa, sa + A_B, bm, bn, M, N, K, s * BK, tid);
    }

    for (int i = 0; i < niter; i++) {
        int rem = niter - 1 - i;
        if (rem >= 2)      asm volatile("cp.async.wait_group 2;\n" ::: "memory");
        else if (rem == 1) asm volatile("cp.async.wait_group 1;\n" ::: "memory");
        else               asm volatile("cp.async.wait_group 0;\n" ::: "memory");
        __syncthreads();

        int s = i % 3;
        uint32_t sa = sbase + s * STAGE_B;
        uint32_t sb = sa + A_B;
#pragma unroll
        for (int ks = 0; ks < 4; ks++) {
            uint32_t a[2][4], b[2][4];
#pragma unroll
            for (int mt = 0; mt < 2; mt++) {
                ldm4(a[mt], sa + 4 * (aoff + mt * 16 * LDS_ + ks * 8));
                if (CVTA) {
#pragma unroll
                    for (int t = 0; t < 4; t++)
                        a[mt][t] = __float_as_uint(tf32_rna(__uint_as_float(a[mt][t])));
                }
            }
#pragma unroll
            for (int np = 0; np < 2; np++)
                ldm4(b[np], sb + 4 * (boff + np * 16 * LDS_ + ks * 8));
#pragma unroll
            for (int mt = 0; mt < 2; mt++)
#pragma unroll
                for (int nt = 0; nt < 4; nt++)
                    mma8(acc[mt][nt], a[mt], b[nt >> 1][(nt & 1) * 2], b[nt >> 1][(nt & 1) * 2 + 1]);
        }
        __syncthreads();
        if (i + 3 < niter)
            load_stage(A, Bm, sa, sb, bm, bn, M, N, K, (i + 3) * BK, tid);
    }

    // epilogue: direct stores, float2 per (row, n-tile)
    int r4 = lane >> 2, c2 = (lane & 3) * 2;
#pragma unroll
    for (int mt = 0; mt < 2; mt++)
#pragma unroll
        for (int nt = 0; nt < 4; nt++) {
            int gr0 = bm + wr * 32 + mt * 16 + r4;
            int gc = bn + wc * 32 + nt * 8 + c2;
            if (gc < N) {
                float2 bb = *reinterpret_cast<const float2*>(&bias[gc]);
#pragma unroll
                for (int hh = 0; hh < 2; hh++) {
                    int gr = gr0 + hh * 8;
                    if (gr < M) {
                        float2 v;
                        v.x = acc[mt][nt][hh * 2 + 0] + bb.x;
                        v.y = acc[mt][nt][hh * 2 + 1] + bb.y;
                        if (MODE == 0) {
                            *reinterpret_cast<float2*>(&C[(size_t)gr * N + gc]) = v;
                        } else {
                            int b = gr / LTOT, l = gr % LTOT;
                            int h = gc >> 5, d = gc & 31;
                            *reinterpret_cast<float2*>(
                                &C[(((size_t)(b * NH + h)) * LTOT + l) * HD + d]) = v;
                        }
                    }
                }
            }
        }
}

// ---------------------------------------------------------------------------
// prep: concat + tf32-round the weights; concat biases (fp32, unrounded)
// ---------------------------------------------------------------------------
__global__ void prep_weights(const float* __restrict__ W_off, const float* __restrict__ b_off,
                             const float* __restrict__ W_attn, const float* __restrict__ b_attn,
                             const float* __restrict__ W_val, const float* __restrict__ W_out) {
    int i = blockIdx.x * blockDim.x + threadIdx.x;
    if (i < 384 * EMBED) g_Wc[i] = tf32_rna(W_off[i]);
    else if (i < NQK * EMBED) g_Wc[i] = tf32_rna(W_attn[i - 384 * EMBED]);
    if (i < EMBED * 2 * EMBED) g_Wvr[i] = tf32_rna(W_val[i]);
    if (i < EMBED * EMBED) g_Wor[i] = tf32_rna(W_out[i]);
    if (i < 384) g_bc[i] = b_off[i];
    else if (i < NQK) g_bc[i] = b_attn[i - 384];
}

// ---------------------------------------------------------------------------
// Bilinear sampling + fused softmax. Output pre-rounded to tf32 for W_out GEMM.
// ---------------------------------------------------------------------------
__global__ void __launch_bounds__(NH * 32)
sample_kernel(const float* __restrict__ ref_l, const float* __restrict__ ref_r,
              const float* __restrict__ offaw, float* __restrict__ out) {
    int bq = blockIdx.x;
    int b = bq / LQ, q = bq % LQ;
    int h = threadIdx.x >> 5;
    int d = threadIdx.x & 31;
    int nqi = q / NK, nki = q % NK;

    const float* rowp = offaw + (size_t)bq * NQK;
    const float* offp = rowp + h * (NL * NP * 4);
    const float* logp = rowp + 384 + h * (NL * NP);
    const float* vb   = g_v + ((size_t)(b * NH + h)) * LTOT * HD + d;

    float wsm[12];
    {
        float m = -1e30f;
#pragma unroll
        for (int i = 0; i < 12; i++) { wsm[i] = __ldg(&logp[i]); m = fmaxf(m, wsm[i]); }
        float s = 0.f;
#pragma unroll
        for (int i = 0; i < 12; i++) { wsm[i] = __expf(wsm[i] - m); s += wsm[i]; }
        float inv = 1.f / s;
#pragma unroll
        for (int i = 0; i < 12; i++) wsm[i] *= inv;
    }

    float acc = 0.f;
#pragma unroll
    for (int l = 0; l < NL; l++) {
        int H = c_lvlH[l], W = c_lvlW[l];
        const float* vlev = vb + (size_t)c_lvlS[l] * HD;
        float fW = (float)W, fH = (float)H;
        size_t rbase = ((((size_t)b * NQ + nqi) * NL + l) * NK + nki) * 2;
        float rlx = __ldg(&ref_l[rbase]);
        float rly = __ldg(&ref_l[rbase + 1]);
        float rrx = __ldg(&ref_r[rbase]);
        float rry = __ldg(&ref_r[rbase + 1]);
#pragma unroll
        for (int p = 0; p < P2; p++) {
            int pp = p & 3;
            int sbase = (l * NP + pp) * 4 + ((p < NP) ? 0 : 2);
            float ox = __ldg(&offp[sbase]);
            float oy = __ldg(&offp[sbase + 1]);
            float w  = wsm[l * NP + pp];
            float lx = ((p < NP) ? rlx : rrx) + ox / fW;
            float ly = ((p < NP) ? rly : rry) + oy / fH;
            float x = lx * fW - 0.5f;
            float y = ly * fH - 0.5f;
            float x0f = floorf(x), y0f = floorf(y);
            int x0 = (int)x0f, y0 = (int)y0f;
            float tx = x - x0f, ty = y - y0f;
            float sval = 0.f;
#pragma unroll
            for (int dy = 0; dy < 2; dy++) {
#pragma unroll
                for (int dx = 0; dx < 2; dx++) {
                    int xi = x0 + dx, yi = y0 + dy;
                    if (xi >= 0 && xi < W && yi >= 0 && yi < H) {
                        float wt = (dx ? tx : 1.f - tx) * (dy ? ty : 1.f - ty);
                        sval += wt * __ldg(&vlev[((size_t)yi * W + xi) * HD]);
                    }
                }
            }
            acc += w * sval;
        }
    }
    out[(size_t)bq * EMBED + h * HD + d] = tf32_rna(acc);
}

extern "C" void kernel_launch(void* const* d_in, const int* in_sizes, int n_in,
                              void* d_out, int out_size) {
    const float* query = (const float*)d_in[0];
    const float* ref_l = (const float*)d_in[1];
    const float* ref_r = (const float*)d_in[2];
    const float* value = (const float*)d_in[3];
    const float* W_off  = (const float*)d_in[6];
    const float* b_off  = (const float*)d_in[7];
    const float* W_attn = (const float*)d_in[8];
    const float* b_attn = (const float*)d_in[9];
    const float* W_val  = (const float*)d_in[10];
    const float* b_val  = (const float*)d_in[11];
    const float* W_out  = (const float*)d_in[12];
    const float* b_out  = (const float*)d_in[13];
    float* out = (float*)d_out;

    float *gv, *goffaw, *gtmp, *gWc, *gbc, *gWvr, *gWor;
    cudaGetSymbolAddress((void**)&gv, g_v);
    cudaGetSymbolAddress((void**)&goffaw, g_offaw);
    cudaGetSymbolAddress((void**)&gtmp, g_tmp);
    cudaGetSymbolAddress((void**)&gWc, g_Wc);
    cudaGetSymbolAddress((void**)&gbc, g_bc);
    cudaGetSymbolAddress((void**)&gWvr, g_Wvr);
    cudaGetSymbolAddress((void**)&gWor, g_Wor);

    cudaFuncSetAttribute(gemm_mma<1,1>, cudaFuncAttributeMaxDynamicSharedMemorySize, GEMM_SMEM);
    cudaFuncSetAttribute(gemm_mma<0,1>, cudaFuncAttributeMaxDynamicSharedMemorySize, GEMM_SMEM);
    cudaFuncSetAttribute(gemm_mma<0,0>, cudaFuncAttributeMaxDynamicSharedMemorySize, GEMM_SMEM);

    // 0. weight prep (round to tf32, concat)
    prep_weights<<<(EMBED * 2 * EMBED + 255) / 256, 256>>>(W_off, b_off, W_attn, b_attn, W_val, W_out);

    // 1. value projection: [MV,512] @ Wv[256,512]^T -> g_v scatter
    {
        dim3 grid(EMBED / BN, (MV + BM - 1) / BM);
        gemm_mma<1,1><<<grid, 256, GEMM_SMEM>>>(value, gWvr, b_val, gv, MV, EMBED, EMBED * 2);
    }
    // 2. fused offsets+logits: [MQ,256] @ Wc[480,256]^T
    {
        dim3 grid((NQK + BN - 1) / BN, (MQ + BM - 1) / BM);
        gemm_mma<0,1><<<grid, 256, GEMM_SMEM>>>(query, gWc, gbc, goffaw, MQ, NQK, EMBED);
    }
    // 3. deformable sampling (+fused softmax), output tf32-rounded
    sample_kernel<<<MQ, NH * 32>>>(ref_l, ref_r, goffaw, gtmp);
    // 4. output projection: [MQ,256] @ Wo[256,256]^T -> d_out
    {
        dim3 grid(EMBED / BN, (MQ + BM - 1) / BM);
        gemm_mma<0,0><<<grid, 256, GEMM_SMEM>>>(gtmp, gWor, b_out, out, MQ, EMBED, EMBED);
    }
}

// round 7
// speedup vs baseline: 2.9130x; 1.9761x over previous
#include <cuda_runtime.h>
#include <cstdint>
#include <math.h>

#define EMBED 256
#define NH 8
#define NL 3
#define NP 4
#define HD 32
#define P2 8
#define B_ 4
#define NQ 300
#define NK 17
#define LQ (NQ * NK)        // 5100
#define LTOT 13125
#define MQ (B_ * LQ)        // 20400
#define MV (B_ * LTOT)      // 52500
#define NQK 480
#define NPTS (NL * P2)      // 24

__constant__ int c_lvlH[NL] = {100, 50, 25};
__constant__ int c_lvlW[NL] = {100, 50, 25};
__constant__ int c_lvlS[NL] = {0, 10000, 12500};

__device__ float g_v[B_ * NH * LTOT * HD];   // [b][h][pix][d]
__device__ float g_offaw[MQ * NQK];
__device__ float g_tmp[MQ * EMBED];
__device__ float g_Wc[NQK * EMBED];          // pre-rounded concat(W_off, W_attn)
__device__ float g_bc[NQK];
__device__ float g_Wvr[EMBED * 2 * EMBED];   // pre-rounded W_val (256x512)
__device__ float g_Wor[EMBED * EMBED];       // pre-rounded W_out

__device__ __forceinline__ float tf32_rna(float x) {
    uint32_t u;
    asm("cvt.rna.tf32.f32 %0, %1;" : "=r"(u) : "f"(x));
    return __uint_as_float(u);
}

__device__ __forceinline__ void cpa16_s(uint32_t s, const float* g, bool pred) {
    int sz = pred ? 16 : 0;
    asm volatile("cp.async.cg.shared.global [%0], [%1], 16, %2;\n" :: "r"(s), "l"(g), "r"(sz));
}

__device__ __forceinline__ void ldm4(uint32_t r[4], uint32_t addr) {
    asm volatile("ldmatrix.sync.aligned.m8n8.x4.shared.b16 {%0,%1,%2,%3}, [%4];"
                 : "=r"(r[0]), "=r"(r[1]), "=r"(r[2]), "=r"(r[3]) : "r"(addr));
}

__device__ __forceinline__ void mma8(float c[4], const uint32_t a[4], uint32_t b0, uint32_t b1) {
    asm volatile("mma.sync.aligned.m16n8k8.row.col.f32.tf32.tf32.f32 "
                 "{%0,%1,%2,%3}, {%4,%5,%6,%7}, {%8,%9}, {%0,%1,%2,%3};"
                 : "+f"(c[0]), "+f"(c[1]), "+f"(c[2]), "+f"(c[3])
                 : "r"(a[0]), "r"(a[1]), "r"(a[2]), "r"(a[3]), "r"(b0), "r"(b1));
}

// ---------------------------------------------------------------------------
// tf32 mma.sync GEMM (unchanged from R6): C[M,N] = A[M,K] @ B[N,K]^T + bias[N]
// ---------------------------------------------------------------------------
#define BM 128
#define BN 64
#define BK 32
#define LDS_ 36
#define STAGE_B ((BM + BN) * LDS_ * 4)
#define A_B (BM * LDS_ * 4)
#define GEMM_SMEM (3 * STAGE_B)

__device__ __forceinline__ void load_stage(
    const float* __restrict__ A, const float* __restrict__ Bm,
    uint32_t sa, uint32_t sb, int bm, int bn, int M, int N, int K, int k0, int tid) {
#pragma unroll
    for (int jj = 0; jj < 4; jj++) {
        int c = tid + 256 * jj;
        int row = c >> 3, kq = c & 7;
        int gr = bm + row;
        bool p = gr < M;
        cpa16_s(sa + (row * LDS_ + kq * 4) * 4, &A[(size_t)(p ? gr : 0) * K + k0 + kq * 4], p);
    }
#pragma unroll
    for (int jj = 0; jj < 2; jj++) {
        int c = tid + 256 * jj;
        int row = c >> 3, kq = c & 7;
        int gc = bn + row;
        bool p = gc < N;
        cpa16_s(sb + (row * LDS_ + kq * 4) * 4, &Bm[(size_t)(p ? gc : 0) * K + k0 + kq * 4], p);
    }
    asm volatile("cp.async.commit_group;\n");
}

template <int MODE, int CVTA>
__global__ void __launch_bounds__(256, 2)
gemm_mma(const float* __restrict__ A, const float* __restrict__ Bm,
         const float* __restrict__ bias, float* __restrict__ C,
         int M, int N, int K) {
    extern __shared__ char smem[];
    uint32_t sbase;
    asm("{ .reg .u64 t; cvta.to.shared.u64 t, %1; cvt.u32.u64 %0, t; }"
        : "=r"(sbase) : "l"(smem));

    int tid = threadIdx.x;
    int warp = tid >> 5, lane = tid & 31;
    int wr = warp >> 1, wc = warp & 1;
    int bm = blockIdx.y * BM, bn = blockIdx.x * BN;

    int j8 = lane >> 3, rr = lane & 7;
    int aoff = (wr * 32 + rr + ((j8 & 1) << 3)) * LDS_ + ((j8 >> 1) << 2);
    int boff = (wc * 32 + rr + ((j8 >> 1) << 3)) * LDS_ + ((j8 & 1) << 2);

    float acc[2][4][4];
#pragma unroll
    for (int i = 0; i < 2; i++)
#pragma unroll
        for (int n = 0; n < 4; n++)
#pragma unroll
            for (int t = 0; t < 4; t++) acc[i][n][t] = 0.f;

    int niter = K / BK;
#pragma unroll
    for (int s = 0; s < 3; s++) {
        uint32_t sa = sbase + s * STAGE_B;
        load_stage(A, Bm, sa, sa + A_B, bm, bn, M, N, K, s * BK, tid);
    }

    for (int i = 0; i < niter; i++) {
        int rem = niter - 1 - i;
        if (rem >= 2)      asm volatile("cp.async.wait_group 2;\n" ::: "memory");
        else if (rem == 1) asm volatile("cp.async.wait_group 1;\n" ::: "memory");
        else               asm volatile("cp.async.wait_group 0;\n" ::: "memory");
        __syncthreads();

        int s = i % 3;
        uint32_t sa = sbase + s * STAGE_B;
        uint32_t sb = sa + A_B;
#pragma unroll
        for (int ks = 0; ks < 4; ks++) {
            uint32_t a[2][4], b[2][4];
#pragma unroll
            for (int mt = 0; mt < 2; mt++) {
                ldm4(a[mt], sa + 4 * (aoff + mt * 16 * LDS_ + ks * 8));
                if (CVTA) {
#pragma unroll
                    for (int t = 0; t < 4; t++)
                        a[mt][t] = __float_as_uint(tf32_rna(__uint_as_float(a[mt][t])));
                }
            }
#pragma unroll
            for (int np = 0; np < 2; np++)
                ldm4(b[np], sb + 4 * (boff + np * 16 * LDS_ + ks * 8));
#pragma unroll
            for (int mt = 0; mt < 2; mt++)
#pragma unroll
                for (int nt = 0; nt < 4; nt++)
                    mma8(acc[mt][nt], a[mt], b[nt >> 1][(nt & 1) * 2], b[nt >> 1][(nt & 1) * 2 + 1]);
        }
        __syncthreads();
        if (i + 3 < niter)
            load_stage(A, Bm, sa, sb, bm, bn, M, N, K, (i + 3) * BK, tid);
    }

    int r4 = lane >> 2, c2 = (lane & 3) * 2;
#pragma unroll
    for (int mt = 0; mt < 2; mt++)
#pragma unroll
        for (int nt = 0; nt < 4; nt++) {
            int gr0 = bm + wr * 32 + mt * 16 + r4;
            int gc = bn + wc * 32 + nt * 8 + c2;
            if (gc < N) {
                float2 bb = *reinterpret_cast<const float2*>(&bias[gc]);
#pragma unroll
                for (int hh = 0; hh < 2; hh++) {
                    int gr = gr0 + hh * 8;
                    if (gr < M) {
                        float2 v;
                        v.x = acc[mt][nt][hh * 2 + 0] + bb.x;
                        v.y = acc[mt][nt][hh * 2 + 1] + bb.y;
                        if (MODE == 0) {
                            *reinterpret_cast<float2*>(&C[(size_t)gr * N + gc]) = v;
                        } else {
                            int b = gr / LTOT, l = gr % LTOT;
                            int h = gc >> 5, d = gc & 31;
                            *reinterpret_cast<float2*>(
                                &C[(((size_t)(b * NH + h)) * LTOT + l) * HD + d]) = v;
                        }
                    }
                }
            }
        }
}

// ---------------------------------------------------------------------------
// prep: concat + tf32-round the weights; concat biases
// ---------------------------------------------------------------------------
__global__ void prep_weights(const float* __restrict__ W_off, const float* __restrict__ b_off,
                             const float* __restrict__ W_attn, const float* __restrict__ b_attn,
                             const float* __restrict__ W_val, const float* __restrict__ W_out) {
    int i = blockIdx.x * blockDim.x + threadIdx.x;
    if (i < 384 * EMBED) g_Wc[i] = tf32_rna(W_off[i]);
    else if (i < NQK * EMBED) g_Wc[i] = tf32_rna(W_attn[i - 384 * EMBED]);
    if (i < EMBED * 2 * EMBED) g_Wvr[i] = tf32_rna(W_val[i]);
    if (i < EMBED * EMBED) g_Wor[i] = tf32_rna(W_out[i]);
    if (i < 384) g_bc[i] = b_off[i];
    else if (i < NQK) g_bc[i] = b_attn[i - 384];
}

// ---------------------------------------------------------------------------
// Sampling v2: lane-parallel scalar prologue + smem-staged gather loop.
// One block per bq; warp = head. Lanes 0..23 each own one sampling point.
// ---------------------------------------------------------------------------
__global__ void __launch_bounds__(NH * 32)
sample_kernel(const float* __restrict__ ref_l, const float* __restrict__ ref_r,
              const float* __restrict__ offaw, float* __restrict__ out) {
    __shared__ float smw[NH][NPTS][4];
    __shared__ int   smi[NH][NPTS][4];

    int bq = blockIdx.x;
    int b = bq / LQ, q = bq % LQ;
    int h = threadIdx.x >> 5;
    int lane = threadIdx.x & 31;
    int nqi = q / NK, nki = q % NK;

    const float* rowp = offaw + (size_t)bq * NQK;
    const float* offp = rowp + h * (NL * NP * 4);
    const float* logp = rowp + 384 + h * (NL * NP);

    // --- softmax over 12 logits, lane-parallel via shuffles ---
    float logit = (lane < 12) ? __ldg(&logp[lane]) : -1e30f;
    float m = logit;
#pragma unroll
    for (int s = 16; s; s >>= 1) m = fmaxf(m, __shfl_xor_sync(0xffffffffu, m, s));
    float e = (lane < 12) ? __expf(logit - m) : 0.f;
    float ssum = e;
#pragma unroll
    for (int s = 16; s; s >>= 1) ssum += __shfl_xor_sync(0xffffffffu, ssum, s);
    float ws = e / ssum;     // lane i holds softmax weight i (i<12)

    // --- per-point prologue (lanes 0..23) ---
    {
        int p = lane;
        int pl = (p < NPTS) ? p : 0;
        int l = pl >> 3;                 // level
        int pr = pl & 7;
        int pp = pr & 3;
        int right = pr >> 2;

        float wp = __shfl_sync(0xffffffffu, ws, l * NP + pp);

        int W = c_lvlW[l], H = c_lvlH[l], S = c_lvlS[l];
        float fW = (float)W, fH = (float)H;

        int rbase = (((b * NQ + nqi) * NL + l) * NK + nki) * 2;
        const float* refp = right ? ref_r : ref_l;
        float rx = __ldg(&refp[rbase]);
        float ry = __ldg(&refp[rbase + 1]);
        int sb = (l * NP + pp) * 4 + right * 2;
        float ox = __ldg(&offp[sb]);
        float oy = __ldg(&offp[sb + 1]);

        float x = fmaf(rx, fW, ox) - 0.5f;
        float y = fmaf(ry, fH, oy) - 0.5f;
        float x0f = floorf(x), y0f = floorf(y);
        int x0 = (int)x0f, y0 = (int)y0f;
        float tx = x - x0f, ty = y - y0f;

        float w4[4];
        int i4[4];
#pragma unroll
        for (int dy = 0; dy < 2; dy++)
#pragma unroll
            for (int dx = 0; dx < 2; dx++) {
                int xi = x0 + dx, yi = y0 + dy;
                bool valid = (xi >= 0) & (xi < W) & (yi >= 0) & (yi < H);
                float wt = (dx ? tx : 1.f - tx) * (dy ? ty : 1.f - ty);
                w4[dy * 2 + dx] = valid ? wp * wt : 0.f;
                i4[dy * 2 + dx] = valid ? (S + yi * W + xi) * HD : 0;
            }
        if (p < NPTS) {
            *reinterpret_cast<float4*>(&smw[h][p][0]) =
                make_float4(w4[0], w4[1], w4[2], w4[3]);
            *reinterpret_cast<int4*>(&smi[h][p][0]) =
                make_int4(i4[0], i4[1], i4[2], i4[3]);
        }
    }
    __syncwarp();

    // --- gather loop: lane = channel d ---
    int d = lane;
    const float* vb = g_v + (b * NH + h) * (LTOT * HD) + d;

    float a0 = 0.f, a1 = 0.f, a2 = 0.f, a3 = 0.f;
#pragma unroll
    for (int p = 0; p < NPTS; p++) {
        float4 wv = *reinterpret_cast<const float4*>(&smw[h][p][0]);
        int4  iv = *reinterpret_cast<const int4*>(&smi[h][p][0]);
        float v0 = __ldg(&vb[iv.x]);
        float v1 = __ldg(&vb[iv.y]);
        float v2 = __ldg(&vb[iv.z]);
        float v3 = __ldg(&vb[iv.w]);
        a0 = fmaf(wv.x, v0, a0);
        a1 = fmaf(wv.y, v1, a1);
        a2 = fmaf(wv.z, v2, a2);
        a3 = fmaf(wv.w, v3, a3);
    }
    out[(size_t)bq * EMBED + h * HD + d] = tf32_rna((a0 + a1) + (a2 + a3));
}

extern "C" void kernel_launch(void* const* d_in, const int* in_sizes, int n_in,
                              void* d_out, int out_size) {
    const float* query = (const float*)d_in[0];
    const float* ref_l = (const float*)d_in[1];
    const float* ref_r = (const float*)d_in[2];
    const float* value = (const float*)d_in[3];
    const float* W_off  = (const float*)d_in[6];
    const float* b_off  = (const float*)d_in[7];
    const float* W_attn = (const float*)d_in[8];
    const float* b_attn = (const float*)d_in[9];
    const float* W_val  = (const float*)d_in[10];
    const float* b_val  = (const float*)d_in[11];
    const float* W_out  = (const float*)d_in[12];
    const float* b_out  = (const float*)d_in[13];
    float* out = (float*)d_out;

    float *gv, *goffaw, *gtmp, *gWc, *gbc, *gWvr, *gWor;
    cudaGetSymbolAddress((void**)&gv, g_v);
    cudaGetSymbolAddress((void**)&goffaw, g_offaw);
    cudaGetSymbolAddress((void**)&gtmp, g_tmp);
    cudaGetSymbolAddress((void**)&gWc, g_Wc);
    cudaGetSymbolAddress((void**)&gbc, g_bc);
    cudaGetSymbolAddress((void**)&gWvr, g_Wvr);
    cudaGetSymbolAddress((void**)&gWor, g_Wor);

    cudaFuncSetAttribute(gemm_mma<1,1>, cudaFuncAttributeMaxDynamicSharedMemorySize, GEMM_SMEM);
    cudaFuncSetAttribute(gemm_mma<0,1>, cudaFuncAttributeMaxDynamicSharedMemorySize, GEMM_SMEM);
    cudaFuncSetAttribute(gemm_mma<0,0>, cudaFuncAttributeMaxDynamicSharedMemorySize, GEMM_SMEM);

    prep_weights<<<(EMBED * 2 * EMBED + 255) / 256, 256>>>(W_off, b_off, W_attn, b_attn, W_val, W_out);

    {
        dim3 grid(EMBED / BN, (MV + BM - 1) / BM);
        gemm_mma<1,1><<<grid, 256, GEMM_SMEM>>>(value, gWvr, b_val, gv, MV, EMBED, EMBED * 2);
    }
    {
        dim3 grid((NQK + BN - 1) / BN, (MQ + BM - 1) / BM);
        gemm_mma<0,1><<<grid, 256, GEMM_SMEM>>>(query, gWc, gbc, goffaw, MQ, NQK, EMBED);
    }
    sample_kernel<<<MQ, NH * 32>>>(ref_l, ref_r, goffaw, gtmp);
    {
        dim3 grid(EMBED / BN, (MQ + BM - 1) / BM);
        gemm_mma<0,0><<<grid, 256, GEMM_SMEM>>>(gtmp, gWor, b_out, out, MQ, EMBED, EMBED);
    }
}

// round 8
// speedup vs baseline: 3.1567x; 1.0837x over previous
#include <cuda_runtime.h>
#include <cstdint>
#include <math.h>

#define EMBED 256
#define NH 8
#define NL 3
#define NP 4
#define HD 32
#define P2 8
#define B_ 4
#define NQ 300
#define NK 17
#define LQ (NQ * NK)        // 5100
#define LTOT 13125
#define MQ (B_ * LQ)        // 20400
#define MV (B_ * LTOT)      // 52500
#define NQK 480
#define NPTS (NL * P2)      // 24

__constant__ int c_lvlH[NL] = {100, 50, 25};
__constant__ int c_lvlW[NL] = {100, 50, 25};
__constant__ int c_lvlS[NL] = {0, 10000, 12500};

__device__ float g_v[B_ * NH * LTOT * HD];   // [b][h][pix][d]
__device__ float g_offaw[MQ * NQK];
__device__ float g_tmp[MQ * EMBED];
__device__ float g_Wc[NQK * EMBED];
__device__ float g_bc[NQK];
__device__ float g_Wvr[EMBED * 2 * EMBED];
__device__ float g_Wor[EMBED * EMBED];

__device__ __forceinline__ float tf32_rna(float x) {
    uint32_t u;
    asm("cvt.rna.tf32.f32 %0, %1;" : "=r"(u) : "f"(x));
    return __uint_as_float(u);
}

__device__ __forceinline__ void cpa16_s(uint32_t s, const float* g, bool pred) {
    int sz = pred ? 16 : 0;
    asm volatile("cp.async.cg.shared.global [%0], [%1], 16, %2;\n" :: "r"(s), "l"(g), "r"(sz));
}

__device__ __forceinline__ void ldm4(uint32_t r[4], uint32_t addr) {
    asm volatile("ldmatrix.sync.aligned.m8n8.x4.shared.b16 {%0,%1,%2,%3}, [%4];"
                 : "=r"(r[0]), "=r"(r[1]), "=r"(r[2]), "=r"(r[3]) : "r"(addr));
}

__device__ __forceinline__ void mma8(float c[4], const uint32_t a[4], uint32_t b0, uint32_t b1) {
    asm volatile("mma.sync.aligned.m16n8k8.row.col.f32.tf32.tf32.f32 "
                 "{%0,%1,%2,%3}, {%4,%5,%6,%7}, {%8,%9}, {%0,%1,%2,%3};"
                 : "+f"(c[0]), "+f"(c[1]), "+f"(c[2]), "+f"(c[3])
                 : "r"(a[0]), "r"(a[1]), "r"(a[2]), "r"(a[3]), "r"(b0), "r"(b1));
}

// ---------------------------------------------------------------------------
// tf32 mma.sync GEMM: C[M,N] = A[M,K] @ B[N,K]^T + bias[N]
// BM=128, BN=128, BK=32; 8 warps (4x2); warp tile 32x64 (2m x 8n x 4k).
// 3-stage cp.async ring. MODE 0: row-major. MODE 1: scatter to g_v layout.
// ---------------------------------------------------------------------------
#define BM 128
#define BN 128
#define BK 32
#define LDS_ 36
#define STAGE_B ((BM + BN) * LDS_ * 4)   // 36864
#define A_B (BM * LDS_ * 4)              // 18432
#define GEMM_SMEM (3 * STAGE_B)          // 110592

__device__ __forceinline__ void load_stage(
    const float* __restrict__ A, const float* __restrict__ Bm,
    uint32_t sa, uint32_t sb, int bm, int bn, int M, int N, int K, int k0, int tid) {
#pragma unroll
    for (int jj = 0; jj < 4; jj++) {
        int c = tid + 256 * jj;
        int row = c >> 3, kq = c & 7;
        int gr = bm + row;
        bool p = gr < M;
        cpa16_s(sa + (row * LDS_ + kq * 4) * 4, &A[(size_t)(p ? gr : 0) * K + k0 + kq * 4], p);
    }
#pragma unroll
    for (int jj = 0; jj < 4; jj++) {
        int c = tid + 256 * jj;
        int row = c >> 3, kq = c & 7;
        int gc = bn + row;
        bool p = gc < N;
        cpa16_s(sb + (row * LDS_ + kq * 4) * 4, &Bm[(size_t)(p ? gc : 0) * K + k0 + kq * 4], p);
    }
    asm volatile("cp.async.commit_group;\n");
}

template <int MODE, int CVTA>
__global__ void __launch_bounds__(256, 2)
gemm_mma(const float* __restrict__ A, const float* __restrict__ Bm,
         const float* __restrict__ bias, float* __restrict__ C,
         int M, int N, int K) {
    extern __shared__ char smem[];
    uint32_t sbase;
    asm("{ .reg .u64 t; cvta.to.shared.u64 t, %1; cvt.u32.u64 %0, t; }"
        : "=r"(sbase) : "l"(smem));

    int tid = threadIdx.x;
    int warp = tid >> 5, lane = tid & 31;
    int wr = warp >> 1, wc = warp & 1;
    int bm = blockIdx.y * BM, bn = blockIdx.x * BN;

    int j8 = lane >> 3, rr = lane & 7;
    int aoff = (wr * 32 + rr + ((j8 & 1) << 3)) * LDS_ + ((j8 >> 1) << 2);
    int boff = (wc * 64 + rr + ((j8 >> 1) << 3)) * LDS_ + ((j8 & 1) << 2);

    float acc[2][8][4];
#pragma unroll
    for (int i = 0; i < 2; i++)
#pragma unroll
        for (int n = 0; n < 8; n++)
#pragma unroll
            for (int t = 0; t < 4; t++) acc[i][n][t] = 0.f;

    int niter = K / BK;
#pragma unroll
    for (int s = 0; s < 3; s++) {
        uint32_t sa = sbase + s * STAGE_B;
        load_stage(A, Bm, sa, sa + A_B, bm, bn, M, N, K, s * BK, tid);
    }

    for (int i = 0; i < niter; i++) {
        int rem = niter - 1 - i;
        if (rem >= 2)      asm volatile("cp.async.wait_group 2;\n" ::: "memory");
        else if (rem == 1) asm volatile("cp.async.wait_group 1;\n" ::: "memory");
        else               asm volatile("cp.async.wait_group 0;\n" ::: "memory");
        __syncthreads();

        int s = i % 3;
        uint32_t sa = sbase + s * STAGE_B;
        uint32_t sb = sa + A_B;
#pragma unroll
        for (int ks = 0; ks < 4; ks++) {
            uint32_t a[2][4], b[4][4];
#pragma unroll
            for (int mt = 0; mt < 2; mt++) {
                ldm4(a[mt], sa + 4 * (aoff + mt * 16 * LDS_ + ks * 8));
                if (CVTA) {
#pragma unroll
                    for (int t = 0; t < 4; t++)
                        a[mt][t] = __float_as_uint(tf32_rna(__uint_as_float(a[mt][t])));
                }
            }
#pragma unroll
            for (int np = 0; np < 4; np++)
                ldm4(b[np], sb + 4 * (boff + np * 16 * LDS_ + ks * 8));
#pragma unroll
            for (int mt = 0; mt < 2; mt++)
#pragma unroll
                for (int nt = 0; nt < 8; nt++)
                    mma8(acc[mt][nt], a[mt], b[nt >> 1][(nt & 1) * 2], b[nt >> 1][(nt & 1) * 2 + 1]);
        }
        __syncthreads();
        if (i + 3 < niter)
            load_stage(A, Bm, sa, sb, bm, bn, M, N, K, (i + 3) * BK, tid);
    }

    int r4 = lane >> 2, c2 = (lane & 3) * 2;
#pragma unroll
    for (int mt = 0; mt < 2; mt++)
#pragma unroll
        for (int nt = 0; nt < 8; nt++) {
            int gr0 = bm + wr * 32 + mt * 16 + r4;
            int gc = bn + wc * 64 + nt * 8 + c2;
            if (gc < N) {
                float2 bb = *reinterpret_cast<const float2*>(&bias[gc]);
#pragma unroll
                for (int hh = 0; hh < 2; hh++) {
                    int gr = gr0 + hh * 8;
                    if (gr < M) {
                        float2 v;
                        v.x = acc[mt][nt][hh * 2 + 0] + bb.x;
                        v.y = acc[mt][nt][hh * 2 + 1] + bb.y;
                        if (MODE == 0) {
                            *reinterpret_cast<float2*>(&C[(size_t)gr * N + gc]) = v;
                        } else {
                            int b = gr / LTOT, l = gr % LTOT;
                            int h = gc >> 5, d = gc & 31;
                            *reinterpret_cast<float2*>(
                                &C[(((size_t)(b * NH + h)) * LTOT + l) * HD + d]) = v;
                        }
                    }
                }
            }
        }
}

// ---------------------------------------------------------------------------
// prep: concat + tf32-round the weights; concat biases
// ---------------------------------------------------------------------------
__global__ void prep_weights(const float* __restrict__ W_off, const float* __restrict__ b_off,
                             const float* __restrict__ W_attn, const float* __restrict__ b_attn,
                             const float* __restrict__ W_val, const float* __restrict__ W_out) {
    int i = blockIdx.x * blockDim.x + threadIdx.x;
    if (i < 384 * EMBED) g_Wc[i] = tf32_rna(W_off[i]);
    else if (i < NQK * EMBED) g_Wc[i] = tf32_rna(W_attn[i - 384 * EMBED]);
    if (i < EMBED * 2 * EMBED) g_Wvr[i] = tf32_rna(W_val[i]);
    if (i < EMBED * EMBED) g_Wor[i] = tf32_rna(W_out[i]);
    if (i < 384) g_bc[i] = b_off[i];
    else if (i < NQK) g_bc[i] = b_attn[i - 384];
}

// ---------------------------------------------------------------------------
// Sampling v3: lane-parallel prologue; gather loop with tap-group float4 loads.
// lane>>3 = tap group g (bilinear corner), lane&7 = channel quad.
// Per point: 1 LDS.64 + 1 LDG.128 + 4 FMA. Cross-group reduce via shuffles.
// ---------------------------------------------------------------------------
#define PPAD 26
__global__ void __launch_bounds__(NH * 32)
sample_kernel(const float* __restrict__ ref_l, const float* __restrict__ ref_r,
              const float* __restrict__ offaw, float* __restrict__ out) {
    __shared__ float2 smp[NH][4][PPAD];    // {w, idx-as-float-bits}

    int bq = blockIdx.x;
    int b = bq / LQ, q = bq % LQ;
    int h = threadIdx.x >> 5;
    int lane = threadIdx.x & 31;
    int nqi = q / NK, nki = q % NK;

    const float* rowp = offaw + (size_t)bq * NQK;
    const float* offp = rowp + h * (NL * NP * 4);
    const float* logp = rowp + 384 + h * (NL * NP);

    // softmax over 12 logits via shuffles
    float logit = (lane < 12) ? __ldg(&logp[lane]) : -1e30f;
    float m = logit;
#pragma unroll
    for (int s = 16; s; s >>= 1) m = fmaxf(m, __shfl_xor_sync(0xffffffffu, m, s));
    float e = (lane < 12) ? __expf(logit - m) : 0.f;
    float ssum = e;
#pragma unroll
    for (int s = 16; s; s >>= 1) ssum += __shfl_xor_sync(0xffffffffu, ssum, s);
    float ws = e / ssum;

    // per-point prologue (lanes 0..23)
    {
        int p = lane;
        int pl = (p < NPTS) ? p : 0;
        int l = pl >> 3;
        int pr = pl & 7;
        int pp = pr & 3;
        int right = pr >> 2;

        float wp = __shfl_sync(0xffffffffu, ws, l * NP + pp);

        int W = c_lvlW[l], H = c_lvlH[l], S = c_lvlS[l];
        float fW = (float)W, fH = (float)H;

        int rbase = (((b * NQ + nqi) * NL + l) * NK + nki) * 2;
        const float* refp = right ? ref_r : ref_l;
        float rx = __ldg(&refp[rbase]);
        float ry = __ldg(&refp[rbase + 1]);
        int sb = (l * NP + pp) * 4 + right * 2;
        float ox = __ldg(&offp[sb]);
        float oy = __ldg(&offp[sb + 1]);

        float x = fmaf(rx, fW, ox) - 0.5f;
        float y = fmaf(ry, fH, oy) - 0.5f;
        float x0f = floorf(x), y0f = floorf(y);
        int x0 = (int)x0f, y0 = (int)y0f;
        float tx = x - x0f, ty = y - y0f;

        if (p < NPTS) {
#pragma unroll
            for (int dy = 0; dy < 2; dy++)
#pragma unroll
                for (int dx = 0; dx < 2; dx++) {
                    int xi = x0 + dx, yi = y0 + dy;
                    bool valid = (xi >= 0) & (xi < W) & (yi >= 0) & (yi < H);
                    float wt = (dx ? tx : 1.f - tx) * (dy ? ty : 1.f - ty);
                    float wv = valid ? wp * wt : 0.f;
                    int iv = valid ? (S + yi * W + xi) * HD : 0;
                    smp[h][dy * 2 + dx][p] = make_float2(wv, __int_as_float(iv));
                }
        }
    }
    __syncwarp();

    // gather loop: lane-group g = tap, lane&7 = channel quad
    int g = lane >> 3, c8 = lane & 7;
    const float* vb = g_v + (b * NH + h) * (LTOT * HD) + c8 * 4;

    float4 a = make_float4(0.f, 0.f, 0.f, 0.f);
#pragma unroll
    for (int p = 0; p < NPTS; p++) {
        float2 wi = smp[h][g][p];
        int idx = __float_as_int(wi.y);
        float4 v = *reinterpret_cast<const float4*>(&vb[idx]);
        a.x = fmaf(wi.x, v.x, a.x);
        a.y = fmaf(wi.x, v.y, a.y);
        a.z = fmaf(wi.x, v.z, a.z);
        a.w = fmaf(wi.x, v.w, a.w);
    }
    // reduce over the 4 tap groups (lanes differing in bits 3,4)
#pragma unroll
    for (int s = 8; s <= 16; s <<= 1) {
        a.x += __shfl_xor_sync(0xffffffffu, a.x, s);
        a.y += __shfl_xor_sync(0xffffffffu, a.y, s);
        a.z += __shfl_xor_sync(0xffffffffu, a.z, s);
        a.w += __shfl_xor_sync(0xffffffffu, a.w, s);
    }
    if (lane < 8) {
        float4 r;
        r.x = tf32_rna(a.x); r.y = tf32_rna(a.y);
        r.z = tf32_rna(a.z); r.w = tf32_rna(a.w);
        *reinterpret_cast<float4*>(&out[(size_t)bq * EMBED + h * HD + lane * 4]) = r;
    }
}

extern "C" void kernel_launch(void* const* d_in, const int* in_sizes, int n_in,
                              void* d_out, int out_size) {
    const float* query = (const float*)d_in[0];
    const float* ref_l = (const float*)d_in[1];
    const float* ref_r = (const float*)d_in[2];
    const float* value = (const float*)d_in[3];
    const float* W_off  = (const float*)d_in[6];
    const float* b_off  = (const float*)d_in[7];
    const float* W_attn = (const float*)d_in[8];
    const float* b_attn = (const float*)d_in[9];
    const float* W_val  = (const float*)d_in[10];
    const float* b_val  = (const float*)d_in[11];
    const float* W_out  = (const float*)d_in[12];
    const float* b_out  = (const float*)d_in[13];
    float* out = (float*)d_out;

    float *gv, *goffaw, *gtmp, *gWc, *gbc, *gWvr, *gWor;
    cudaGetSymbolAddress((void**)&gv, g_v);
    cudaGetSymbolAddress((void**)&goffaw, g_offaw);
    cudaGetSymbolAddress((void**)&gtmp, g_tmp);
    cudaGetSymbolAddress((void**)&gWc, g_Wc);
    cudaGetSymbolAddress((void**)&gbc, g_bc);
    cudaGetSymbolAddress((void**)&gWvr, g_Wvr);
    cudaGetSymbolAddress((void**)&gWor, g_Wor);

    cudaFuncSetAttribute(gemm_mma<1,1>, cudaFuncAttributeMaxDynamicSharedMemorySize, GEMM_SMEM);
    cudaFuncSetAttribute(gemm_mma<0,1>, cudaFuncAttributeMaxDynamicSharedMemorySize, GEMM_SMEM);
    cudaFuncSetAttribute(gemm_mma<0,0>, cudaFuncAttributeMaxDynamicSharedMemorySize, GEMM_SMEM);

    prep_weights<<<(EMBED * 2 * EMBED + 255) / 256, 256>>>(W_off, b_off, W_attn, b_attn, W_val, W_out);

    {
        dim3 grid(EMBED / BN, (MV + BM - 1) / BM);
        gemm_mma<1,1><<<grid, 256, GEMM_SMEM>>>(value, gWvr, b_val, gv, MV, EMBED, EMBED * 2);
    }
    {
        dim3 grid((NQK + BN - 1) / BN, (MQ + BM - 1) / BM);
        gemm_mma<0,1><<<grid, 256, GEMM_SMEM>>>(query, gWc, gbc, goffaw, MQ, NQK, EMBED);
    }
    sample_kernel<<<MQ, NH * 32>>>(ref_l, ref_r, goffaw, gtmp);
    {
        dim3 grid(EMBED / BN, (MQ + BM - 1) / BM);
        gemm_mma<0,0><<<grid, 256, GEMM_SMEM>>>(gtmp, gWor, b_out, out, MQ, EMBED, EMBED);
    }
}

// round 9
// speedup vs baseline: 3.6270x; 1.1490x over previous
#include <cuda_runtime.h>
#include <cuda_fp16.h>
#include <cstdint>
#include <math.h>

#define EMBED 256
#define NH 8
#define NL 3
#define NP 4
#define HD 32
#define P2 8
#define B_ 4
#define NQ 300
#define NK 17
#define LQ (NQ * NK)        // 5100
#define LTOT 13125
#define MQ (B_ * LQ)        // 20400
#define MV (B_ * LTOT)      // 52500
#define NQK 480
#define NPTS (NL * P2)      // 24

__constant__ int c_lvlH[NL] = {100, 50, 25};
__constant__ int c_lvlW[NL] = {100, 50, 25};
__constant__ int c_lvlS[NL] = {0, 10000, 12500};

__device__ float  g_v[B_ * NH * LTOT * HD];   // [b][h][pix][d] fp32
__device__ float  g_offaw[MQ * NQK];
__device__ __half g_valh[MV * EMBED * 2];     // fp16 value
__device__ __half g_qh[MQ * EMBED];           // fp16 query
__device__ __half g_tmph[MQ * EMBED];         // fp16 sampled output
__device__ __half g_Wch[NQK * EMBED];
__device__ float  g_bc[NQK];
__device__ __half g_Wvh[EMBED * 2 * EMBED];
__device__ __half g_Woh[EMBED * EMBED];

__device__ __forceinline__ void cpa16_s(uint32_t s, const void* g, bool pred) {
    int sz = pred ? 16 : 0;
    asm volatile("cp.async.cg.shared.global [%0], [%1], 16, %2;\n" :: "r"(s), "l"(g), "r"(sz));
}

__device__ __forceinline__ void ldm4(uint32_t r[4], uint32_t addr) {
    asm volatile("ldmatrix.sync.aligned.m8n8.x4.shared.b16 {%0,%1,%2,%3}, [%4];"
                 : "=r"(r[0]), "=r"(r[1]), "=r"(r[2]), "=r"(r[3]) : "r"(addr));
}

__device__ __forceinline__ void mma16816(float c[4], const uint32_t a[4], uint32_t b0, uint32_t b1) {
    asm volatile("mma.sync.aligned.m16n8k16.row.col.f32.f16.f16.f32 "
                 "{%0,%1,%2,%3}, {%4,%5,%6,%7}, {%8,%9}, {%0,%1,%2,%3};"
                 : "+f"(c[0]), "+f"(c[1]), "+f"(c[2]), "+f"(c[3])
                 : "r"(a[0]), "r"(a[1]), "r"(a[2]), "r"(a[3]), "r"(b0), "r"(b1));
}

// ---------------------------------------------------------------------------
// fp16 mma.sync GEMM: C[M,N] = A[M,K] @ B[N,K]^T + bias[N]   (A,B fp16; C fp32)
// BM=128, BN=128, BK=64 halfs; 8 warps (4x2), warp tile 32x64.
// 3-stage cp.async ring. MODE 0: row-major. MODE 1: scatter to g_v layout.
// ---------------------------------------------------------------------------
#define BM 128
#define BN 128
#define BKH 64
#define LDS_H 72                          // 144B row stride: conflict-free ldmatrix
#define STAGE_B ((BM + BN) * LDS_H * 2)   // 36864
#define A_B (BM * LDS_H * 2)              // 18432
#define GEMM_SMEM (3 * STAGE_B)           // 110592

__device__ __forceinline__ void load_stage(
    const __half* __restrict__ A, const __half* __restrict__ Bm,
    uint32_t sa, uint32_t sb, int bm, int bn, int M, int N, int K, int k0, int tid) {
#pragma unroll
    for (int jj = 0; jj < 4; jj++) {       // A: 128 rows x 8 chunks(8 halfs)
        int c = tid + 256 * jj;
        int row = c >> 3, q = c & 7;
        int gr = bm + row;
        bool p = gr < M;
        cpa16_s(sa + (row * LDS_H + q * 8) * 2, &A[(size_t)(p ? gr : 0) * K + k0 + q * 8], p);
    }
#pragma unroll
    for (int jj = 0; jj < 4; jj++) {       // B: 128 rows x 8 chunks
        int c = tid + 256 * jj;
        int row = c >> 3, q = c & 7;
        int gc = bn + row;
        bool p = gc < N;
        cpa16_s(sb + (row * LDS_H + q * 8) * 2, &Bm[(size_t)(p ? gc : 0) * K + k0 + q * 8], p);
    }
    asm volatile("cp.async.commit_group;\n");
}

template <int MODE>
__global__ void __launch_bounds__(256, 2)
gemm_h(const __half* __restrict__ A, const __half* __restrict__ Bm,
       const float* __restrict__ bias, float* __restrict__ C,
       int M, int N, int K) {
    extern __shared__ char smem[];
    uint32_t sbase;
    asm("{ .reg .u64 t; cvta.to.shared.u64 t, %1; cvt.u32.u64 %0, t; }"
        : "=r"(sbase) : "l"(smem));

    int tid = threadIdx.x;
    int warp = tid >> 5, lane = tid & 31;
    int wr = warp >> 1, wc = warp & 1;
    int bm = blockIdx.y * BM, bn = blockIdx.x * BN;

    // ldmatrix octet mapping: row += (j8&1)*8, kcol += (j8>>1)*8
    int j8 = lane >> 3, rr = lane & 7;
    int rowx = rr + ((j8 & 1) << 3);
    int colx = (j8 >> 1) << 3;

    float acc[2][8][4];
#pragma unroll
    for (int i = 0; i < 2; i++)
#pragma unroll
        for (int n = 0; n < 8; n++)
#pragma unroll
            for (int t = 0; t < 4; t++) acc[i][n][t] = 0.f;

    int niter = K / BKH;
#pragma unroll
    for (int s = 0; s < 3; s++) {
        uint32_t sa = sbase + s * STAGE_B;
        load_stage(A, Bm, sa, sa + A_B, bm, bn, M, N, K, s * BKH, tid);
    }

    for (int i = 0; i < niter; i++) {
        int rem = niter - 1 - i;
        if (rem >= 2)      asm volatile("cp.async.wait_group 2;\n" ::: "memory");
        else if (rem == 1) asm volatile("cp.async.wait_group 1;\n" ::: "memory");
        else               asm volatile("cp.async.wait_group 0;\n" ::: "memory");
        __syncthreads();

        int s = i % 3;
        uint32_t sa = sbase + s * STAGE_B;
        uint32_t sb = sa + A_B;
#pragma unroll
        for (int ks = 0; ks < 4; ks++) {          // 4 x k16 per block
            int kc = ks * 16 + colx;
            uint32_t a[2][4], b[4][4];
#pragma unroll
            for (int mt = 0; mt < 2; mt++)
                ldm4(a[mt], sa + ((wr * 32 + mt * 16 + rowx) * LDS_H + kc) * 2);
#pragma unroll
            for (int np = 0; np < 4; np++)
                ldm4(b[np], sb + ((wc * 64 + np * 16 + rowx) * LDS_H + kc) * 2);
#pragma unroll
            for (int mt = 0; mt < 2; mt++)
#pragma unroll
                for (int nf = 0; nf < 8; nf++)
                    mma16816(acc[mt][nf], a[mt],
                             b[nf >> 1][nf & 1], b[nf >> 1][2 + (nf & 1)]);
        }
        __syncthreads();
        if (i + 3 < niter)
            load_stage(A, Bm, sa, sb, bm, bn, M, N, K, (i + 3) * BKH, tid);
    }

    int r4 = lane >> 2, c2 = (lane & 3) * 2;
#pragma unroll
    for (int mt = 0; mt < 2; mt++)
#pragma unroll
        for (int nf = 0; nf < 8; nf++) {
            int gr0 = bm + wr * 32 + mt * 16 + r4;
            int gc = bn + wc * 64 + nf * 8 + c2;
            if (gc < N) {
                float2 bb = *reinterpret_cast<const float2*>(&bias[gc]);
#pragma unroll
                for (int hh = 0; hh < 2; hh++) {
                    int gr = gr0 + hh * 8;
                    if (gr < M) {
                        float2 v;
                        v.x = acc[mt][nf][hh * 2 + 0] + bb.x;
                        v.y = acc[mt][nf][hh * 2 + 1] + bb.y;
                        if (MODE == 0) {
                            *reinterpret_cast<float2*>(&C[(size_t)gr * N + gc]) = v;
                        } else {
                            int b = gr / LTOT, l = gr % LTOT;
                            int h = gc >> 5, d = gc & 31;
                            *reinterpret_cast<float2*>(
                                &C[(((size_t)(b * NH + h)) * LTOT + l) * HD + d]) = v;
                        }
                    }
                }
            }
        }
}

// ---------------------------------------------------------------------------
// converts + weight prep
// ---------------------------------------------------------------------------
__global__ void f32_to_f16(const float* __restrict__ src, __half* __restrict__ dst, int n4) {
    int i = blockIdx.x * blockDim.x + threadIdx.x;
    if (i < n4) {
        float4 v = reinterpret_cast<const float4*>(src)[i];
        __half2 h0 = __floats2half2_rn(v.x, v.y);
        __half2 h1 = __floats2half2_rn(v.z, v.w);
        reinterpret_cast<__half2*>(dst)[i * 2] = h0;
        reinterpret_cast<__half2*>(dst)[i * 2 + 1] = h1;
    }
}

__global__ void prep_weights(const float* __restrict__ W_off, const float* __restrict__ b_off,
                             const float* __restrict__ W_attn, const float* __restrict__ b_attn,
                             const float* __restrict__ W_val, const float* __restrict__ W_out) {
    int i = blockIdx.x * blockDim.x + threadIdx.x;
    if (i < 384 * EMBED) g_Wch[i] = __float2half_rn(W_off[i]);
    else if (i < NQK * EMBED) g_Wch[i] = __float2half_rn(W_attn[i - 384 * EMBED]);
    if (i < EMBED * 2 * EMBED) g_Wvh[i] = __float2half_rn(W_val[i]);
    if (i < EMBED * EMBED) g_Woh[i] = __float2half_rn(W_out[i]);
    if (i < 384) g_bc[i] = b_off[i];
    else if (i < NQK) g_bc[i] = b_attn[i - 384];
}

// ---------------------------------------------------------------------------
// Sampling (R8 structure); output stored as fp16 for the W_out GEMM.
// ---------------------------------------------------------------------------
#define PPAD 26
__global__ void __launch_bounds__(NH * 32)
sample_kernel(const float* __restrict__ ref_l, const float* __restrict__ ref_r,
              const float* __restrict__ offaw, __half* __restrict__ out) {
    __shared__ float2 smp[NH][4][PPAD];

    int bq = blockIdx.x;
    int b = bq / LQ, q = bq % LQ;
    int h = threadIdx.x >> 5;
    int lane = threadIdx.x & 31;
    int nqi = q / NK, nki = q % NK;

    const float* rowp = offaw + (size_t)bq * NQK;
    const float* offp = rowp + h * (NL * NP * 4);
    const float* logp = rowp + 384 + h * (NL * NP);

    float logit = (lane < 12) ? __ldg(&logp[lane]) : -1e30f;
    float m = logit;
#pragma unroll
    for (int s = 16; s; s >>= 1) m = fmaxf(m, __shfl_xor_sync(0xffffffffu, m, s));
    float e = (lane < 12) ? __expf(logit - m) : 0.f;
    float ssum = e;
#pragma unroll
    for (int s = 16; s; s >>= 1) ssum += __shfl_xor_sync(0xffffffffu, ssum, s);
    float ws = e / ssum;

    {
        int p = lane;
        int pl = (p < NPTS) ? p : 0;
        int l = pl >> 3;
        int pr = pl & 7;
        int pp = pr & 3;
        int right = pr >> 2;

        float wp = __shfl_sync(0xffffffffu, ws, l * NP + pp);

        int W = c_lvlW[l], H = c_lvlH[l], S = c_lvlS[l];
        float fW = (float)W, fH = (float)H;

        int rbase = (((b * NQ + nqi) * NL + l) * NK + nki) * 2;
        const float* refp = right ? ref_r : ref_l;
        float rx = __ldg(&refp[rbase]);
        float ry = __ldg(&refp[rbase + 1]);
        int sb = (l * NP + pp) * 4 + right * 2;
        float ox = __ldg(&offp[sb]);
        float oy = __ldg(&offp[sb + 1]);

        float x = fmaf(rx, fW, ox) - 0.5f;
        float y = fmaf(ry, fH, oy) - 0.5f;
        float x0f = floorf(x), y0f = floorf(y);
        int x0 = (int)x0f, y0 = (int)y0f;
        float tx = x - x0f, ty = y - y0f;

        if (p < NPTS) {
#pragma unroll
            for (int dy = 0; dy < 2; dy++)
#pragma unroll
                for (int dx = 0; dx < 2; dx++) {
                    int xi = x0 + dx, yi = y0 + dy;
                    bool valid = (xi >= 0) & (xi < W) & (yi >= 0) & (yi < H);
                    float wt = (dx ? tx : 1.f - tx) * (dy ? ty : 1.f - ty);
                    float wv = valid ? wp * wt : 0.f;
                    int iv = valid ? (S + yi * W + xi) * HD : 0;
                    smp[h][dy * 2 + dx][p] = make_float2(wv, __int_as_float(iv));
                }
        }
    }
    __syncwarp();

    int g = lane >> 3, c8 = lane & 7;
    const float* vb = g_v + (b * NH + h) * (LTOT * HD) + c8 * 4;

    float4 a = make_float4(0.f, 0.f, 0.f, 0.f);
#pragma unroll
    for (int p = 0; p < NPTS; p++) {
        float2 wi = smp[h][g][p];
        int idx = __float_as_int(wi.y);
        float4 v = *reinterpret_cast<const float4*>(&vb[idx]);
        a.x = fmaf(wi.x, v.x, a.x);
        a.y = fmaf(wi.x, v.y, a.y);
        a.z = fmaf(wi.x, v.z, a.z);
        a.w = fmaf(wi.x, v.w, a.w);
    }
#pragma unroll
    for (int s = 8; s <= 16; s <<= 1) {
        a.x += __shfl_xor_sync(0xffffffffu, a.x, s);
        a.y += __shfl_xor_sync(0xffffffffu, a.y, s);
        a.z += __shfl_xor_sync(0xffffffffu, a.z, s);
        a.w += __shfl_xor_sync(0xffffffffu, a.w, s);
    }
    if (lane < 8) {
        __half2 h0 = __floats2half2_rn(a.x, a.y);
        __half2 h1 = __floats2half2_rn(a.z, a.w);
        __half2* op = reinterpret_cast<__half2*>(&out[(size_t)bq * EMBED + h * HD + lane * 4]);
        op[0] = h0; op[1] = h1;
    }
}

extern "C" void kernel_launch(void* const* d_in, const int* in_sizes, int n_in,
                              void* d_out, int out_size) {
    const float* query = (const float*)d_in[0];
    const float* ref_l = (const float*)d_in[1];
    const float* ref_r = (const float*)d_in[2];
    const float* value = (const float*)d_in[3];
    const float* W_off  = (const float*)d_in[6];
    const float* b_off  = (const float*)d_in[7];
    const float* W_attn = (const float*)d_in[8];
    const float* b_attn = (const float*)d_in[9];
    const float* W_val  = (const float*)d_in[10];
    const float* b_val  = (const float*)d_in[11];
    const float* W_out  = (const float*)d_in[12];
    const float* b_out  = (const float*)d_in[13];
    float* out = (float*)d_out;

    float *gv, *goffaw, *gbc;
    __half *gvalh, *gqh, *gtmph, *gWch, *gWvh, *gWoh;
    cudaGetSymbolAddress((void**)&gv, g_v);
    cudaGetSymbolAddress((void**)&goffaw, g_offaw);
    cudaGetSymbolAddress((void**)&gbc, g_bc);
    cudaGetSymbolAddress((void**)&gvalh, g_valh);
    cudaGetSymbolAddress((void**)&gqh, g_qh);
    cudaGetSymbolAddress((void**)&gtmph, g_tmph);
    cudaGetSymbolAddress((void**)&gWch, g_Wch);
    cudaGetSymbolAddress((void**)&gWvh, g_Wvh);
    cudaGetSymbolAddress((void**)&gWoh, g_Woh);

    cudaFuncSetAttribute(gemm_h<1>, cudaFuncAttributeMaxDynamicSharedMemorySize, GEMM_SMEM);
    cudaFuncSetAttribute(gemm_h<0>, cudaFuncAttributeMaxDynamicSharedMemorySize, GEMM_SMEM);

    prep_weights<<<(EMBED * 2 * EMBED + 255) / 256, 256>>>(W_off, b_off, W_attn, b_attn, W_val, W_out);
    f32_to_f16<<<(MV * EMBED * 2 / 4 + 255) / 256, 256>>>(value, gvalh, MV * EMBED * 2 / 4);
    f32_to_f16<<<(MQ * EMBED / 4 + 255) / 256, 256>>>(query, gqh, MQ * EMBED / 4);

    // 1. value projection: [MV,512] @ Wv[256,512]^T -> g_v scatter
    {
        dim3 grid(EMBED / BN, (MV + BM - 1) / BM);
        gemm_h<1><<<grid, 256, GEMM_SMEM>>>(gvalh, gWvh, b_val, gv, MV, EMBED, EMBED * 2);
    }
    // 2. fused offsets+logits: [MQ,256] @ Wc[480,256]^T
    {
        dim3 grid((NQK + BN - 1) / BN, (MQ + BM - 1) / BM);
        gemm_h<0><<<grid, 256, GEMM_SMEM>>>(gqh, gWch, gbc, goffaw, MQ, NQK, EMBED);
    }
    // 3. deformable sampling (+fused softmax), fp16 output
    sample_kernel<<<MQ, NH * 32>>>(ref_l, ref_r, goffaw, gtmph);
    // 4. output projection: [MQ,256] @ Wo[256,256]^T -> d_out
    {
        dim3 grid(EMBED / BN, (MQ + BM - 1) / BM);
        gemm_h<0><<<grid, 256, GEMM_SMEM>>>(gtmph, gWoh, b_out, out, MQ, EMBED, EMBED);
    }
}

// round 10
// speedup vs baseline: 3.7984x; 1.0472x over previous
#include <cuda_runtime.h>
#include <cuda_fp16.h>
#include <cstdint>
#include <math.h>

#define EMBED 256
#define NH 8
#define NL 3
#define NP 4
#define HD 32
#define P2 8
#define B_ 4
#define NQ 300
#define NK 17
#define LQ (NQ * NK)        // 5100
#define LTOT 13125
#define MQ (B_ * LQ)        // 20400
#define MV (B_ * LTOT)      // 52500
#define NQK 480
#define NPTS (NL * P2)      // 24

__constant__ int c_lvlH[NL] = {100, 50, 25};
__constant__ int c_lvlW[NL] = {100, 50, 25};
__constant__ int c_lvlS[NL] = {0, 10000, 12500};

__device__ __half g_vh[B_ * NH * LTOT * HD];  // [b][h][pix][d] fp16 (26.9 MB, L2-resident)
__device__ float  g_offaw[MQ * NQK];
__device__ __half g_valh[MV * EMBED * 2];
__device__ __half g_qh[MQ * EMBED];
__device__ __half g_tmph[MQ * EMBED];
__device__ __half g_Wch[NQK * EMBED];
__device__ float  g_bc[NQK];
__device__ __half g_Wvh[EMBED * 2 * EMBED];
__device__ __half g_Woh[EMBED * EMBED];

__device__ __forceinline__ void cpa16_s(uint32_t s, const void* g, bool pred) {
    int sz = pred ? 16 : 0;
    asm volatile("cp.async.cg.shared.global [%0], [%1], 16, %2;\n" :: "r"(s), "l"(g), "r"(sz));
}

__device__ __forceinline__ void ldm4(uint32_t r[4], uint32_t addr) {
    asm volatile("ldmatrix.sync.aligned.m8n8.x4.shared.b16 {%0,%1,%2,%3}, [%4];"
                 : "=r"(r[0]), "=r"(r[1]), "=r"(r[2]), "=r"(r[3]) : "r"(addr));
}

__device__ __forceinline__ void mma16816(float c[4], const uint32_t a[4], uint32_t b0, uint32_t b1) {
    asm volatile("mma.sync.aligned.m16n8k16.row.col.f32.f16.f16.f32 "
                 "{%0,%1,%2,%3}, {%4,%5,%6,%7}, {%8,%9}, {%0,%1,%2,%3};"
                 : "+f"(c[0]), "+f"(c[1]), "+f"(c[2]), "+f"(c[3])
                 : "r"(a[0]), "r"(a[1]), "r"(a[2]), "r"(a[3]), "r"(b0), "r"(b1));
}

// ---------------------------------------------------------------------------
// fp16 mma.sync GEMM: C[M,N] = A[M,K] @ B[N,K]^T + bias[N]
// BM=128, BN=128, BK=64 halfs; 8 warps (4x2), warp tile 32x64. 3-stage ring.
// MODE 0: fp32 row-major. MODE 1: fp16 scatter to g_vh layout [b][h][pix][d].
// ---------------------------------------------------------------------------
#define BM 128
#define BN 128
#define BKH 64
#define LDS_H 72
#define STAGE_B ((BM + BN) * LDS_H * 2)   // 36864
#define A_B (BM * LDS_H * 2)
#define GEMM_SMEM (3 * STAGE_B)           // 110592

__device__ __forceinline__ void load_stage(
    const __half* __restrict__ A, const __half* __restrict__ Bm,
    uint32_t sa, uint32_t sb, int bm, int bn, int M, int N, int K, int k0, int tid) {
#pragma unroll
    for (int jj = 0; jj < 4; jj++) {
        int c = tid + 256 * jj;
        int row = c >> 3, q = c & 7;
        int gr = bm + row;
        bool p = gr < M;
        cpa16_s(sa + (row * LDS_H + q * 8) * 2, &A[(size_t)(p ? gr : 0) * K + k0 + q * 8], p);
    }
#pragma unroll
    for (int jj = 0; jj < 4; jj++) {
        int c = tid + 256 * jj;
        int row = c >> 3, q = c & 7;
        int gc = bn + row;
        bool p = gc < N;
        cpa16_s(sb + (row * LDS_H + q * 8) * 2, &Bm[(size_t)(p ? gc : 0) * K + k0 + q * 8], p);
    }
    asm volatile("cp.async.commit_group;\n");
}

template <int MODE>
__global__ void __launch_bounds__(256, 2)
gemm_h(const __half* __restrict__ A, const __half* __restrict__ Bm,
       const float* __restrict__ bias, void* __restrict__ Cv,
       int M, int N, int K) {
    extern __shared__ char smem[];
    uint32_t sbase;
    asm("{ .reg .u64 t; cvta.to.shared.u64 t, %1; cvt.u32.u64 %0, t; }"
        : "=r"(sbase) : "l"(smem));

    int tid = threadIdx.x;
    int warp = tid >> 5, lane = tid & 31;
    int wr = warp >> 1, wc = warp & 1;
    int bm = blockIdx.y * BM, bn = blockIdx.x * BN;

    int j8 = lane >> 3, rr = lane & 7;
    int rowx = rr + ((j8 & 1) << 3);
    int colx = (j8 >> 1) << 3;

    float acc[2][8][4];
#pragma unroll
    for (int i = 0; i < 2; i++)
#pragma unroll
        for (int n = 0; n < 8; n++)
#pragma unroll
            for (int t = 0; t < 4; t++) acc[i][n][t] = 0.f;

    int niter = K / BKH;
#pragma unroll
    for (int s = 0; s < 3; s++) {
        uint32_t sa = sbase + s * STAGE_B;
        load_stage(A, Bm, sa, sa + A_B, bm, bn, M, N, K, s * BKH, tid);
    }

    for (int i = 0; i < niter; i++) {
        int rem = niter - 1 - i;
        if (rem >= 2)      asm volatile("cp.async.wait_group 2;\n" ::: "memory");
        else if (rem == 1) asm volatile("cp.async.wait_group 1;\n" ::: "memory");
        else               asm volatile("cp.async.wait_group 0;\n" ::: "memory");
        __syncthreads();

        int s = i % 3;
        uint32_t sa = sbase + s * STAGE_B;
        uint32_t sb = sa + A_B;
#pragma unroll
        for (int ks = 0; ks < 4; ks++) {
            int kc = ks * 16 + colx;
            uint32_t a[2][4], b[4][4];
#pragma unroll
            for (int mt = 0; mt < 2; mt++)
                ldm4(a[mt], sa + ((wr * 32 + mt * 16 + rowx) * LDS_H + kc) * 2);
#pragma unroll
            for (int np = 0; np < 4; np++)
                ldm4(b[np], sb + ((wc * 64 + np * 16 + rowx) * LDS_H + kc) * 2);
#pragma unroll
            for (int mt = 0; mt < 2; mt++)
#pragma unroll
                for (int nf = 0; nf < 8; nf++)
                    mma16816(acc[mt][nf], a[mt],
                             b[nf >> 1][nf & 1], b[nf >> 1][2 + (nf & 1)]);
        }
        __syncthreads();
        if (i + 3 < niter)
            load_stage(A, Bm, sa, sb, bm, bn, M, N, K, (i + 3) * BKH, tid);
    }

    int r4 = lane >> 2, c2 = (lane & 3) * 2;
#pragma unroll
    for (int mt = 0; mt < 2; mt++)
#pragma unroll
        for (int nf = 0; nf < 8; nf++) {
            int gr0 = bm + wr * 32 + mt * 16 + r4;
            int gc = bn + wc * 64 + nf * 8 + c2;
            if (gc < N) {
                float2 bb = *reinterpret_cast<const float2*>(&bias[gc]);
#pragma unroll
                for (int hh = 0; hh < 2; hh++) {
                    int gr = gr0 + hh * 8;
                    if (gr < M) {
                        float vx = acc[mt][nf][hh * 2 + 0] + bb.x;
                        float vy = acc[mt][nf][hh * 2 + 1] + bb.y;
                        if (MODE == 0) {
                            *reinterpret_cast<float2*>(
                                &((float*)Cv)[(size_t)gr * N + gc]) = make_float2(vx, vy);
                        } else {
                            int b = gr / LTOT, l = gr % LTOT;
                            int h = gc >> 5, d = gc & 31;
                            *reinterpret_cast<__half2*>(
                                &((__half*)Cv)[(((size_t)(b * NH + h)) * LTOT + l) * HD + d]) =
                                __floats2half2_rn(vx, vy);
                        }
                    }
                }
            }
        }
}

// ---------------------------------------------------------------------------
// converts + weight prep
// ---------------------------------------------------------------------------
__global__ void f32_to_f16(const float* __restrict__ src, __half* __restrict__ dst, int n4) {
    int i = blockIdx.x * blockDim.x + threadIdx.x;
    if (i < n4) {
        float4 v = reinterpret_cast<const float4*>(src)[i];
        reinterpret_cast<__half2*>(dst)[i * 2] = __floats2half2_rn(v.x, v.y);
        reinterpret_cast<__half2*>(dst)[i * 2 + 1] = __floats2half2_rn(v.z, v.w);
    }
}

__global__ void prep_weights(const float* __restrict__ W_off, const float* __restrict__ b_off,
                             const float* __restrict__ W_attn, const float* __restrict__ b_attn,
                             const float* __restrict__ W_val, const float* __restrict__ W_out) {
    int i = blockIdx.x * blockDim.x + threadIdx.x;
    if (i < 384 * EMBED) g_Wch[i] = __float2half_rn(W_off[i]);
    else if (i < NQK * EMBED) g_Wch[i] = __float2half_rn(W_attn[i - 384 * EMBED]);
    if (i < EMBED * 2 * EMBED) g_Wvh[i] = __float2half_rn(W_val[i]);
    if (i < EMBED * EMBED) g_Woh[i] = __float2half_rn(W_out[i]);
    if (i < 384) g_bc[i] = b_off[i];
    else if (i < NQK) g_bc[i] = b_attn[i - 384];
}

// ---------------------------------------------------------------------------
// Sampling: fp16 gathers (64B per tap). lane>>3 = tap, lane&7 = channel quad.
// ---------------------------------------------------------------------------
#define PPAD 26
__global__ void __launch_bounds__(NH * 32)
sample_kernel(const float* __restrict__ ref_l, const float* __restrict__ ref_r,
              const float* __restrict__ offaw, __half* __restrict__ out) {
    __shared__ float2 smp[NH][4][PPAD];

    int bq = blockIdx.x;
    int b = bq / LQ, q = bq % LQ;
    int h = threadIdx.x >> 5;
    int lane = threadIdx.x & 31;
    int nqi = q / NK, nki = q % NK;

    const float* rowp = offaw + (size_t)bq * NQK;
    const float* offp = rowp + h * (NL * NP * 4);
    const float* logp = rowp + 384 + h * (NL * NP);

    float logit = (lane < 12) ? __ldg(&logp[lane]) : -1e30f;
    float m = logit;
#pragma unroll
    for (int s = 16; s; s >>= 1) m = fmaxf(m, __shfl_xor_sync(0xffffffffu, m, s));
    float e = (lane < 12) ? __expf(logit - m) : 0.f;
    float ssum = e;
#pragma unroll
    for (int s = 16; s; s >>= 1) ssum += __shfl_xor_sync(0xffffffffu, ssum, s);
    float ws = e / ssum;

    {
        int p = lane;
        int pl = (p < NPTS) ? p : 0;
        int l = pl >> 3;
        int pr = pl & 7;
        int pp = pr & 3;
        int right = pr >> 2;

        float wp = __shfl_sync(0xffffffffu, ws, l * NP + pp);

        int W = c_lvlW[l], H = c_lvlH[l], S = c_lvlS[l];
        float fW = (float)W, fH = (float)H;

        int rbase = (((b * NQ + nqi) * NL + l) * NK + nki) * 2;
        const float* refp = right ? ref_r : ref_l;
        float rx = __ldg(&refp[rbase]);
        float ry = __ldg(&refp[rbase + 1]);
        int sb = (l * NP + pp) * 4 + right * 2;
        float ox = __ldg(&offp[sb]);
        float oy = __ldg(&offp[sb + 1]);

        float x = fmaf(rx, fW, ox) - 0.5f;
        float y = fmaf(ry, fH, oy) - 0.5f;
        float x0f = floorf(x), y0f = floorf(y);
        int x0 = (int)x0f, y0 = (int)y0f;
        float tx = x - x0f, ty = y - y0f;

        if (p < NPTS) {
#pragma unroll
            for (int dy = 0; dy < 2; dy++)
#pragma unroll
                for (int dx = 0; dx < 2; dx++) {
                    int xi = x0 + dx, yi = y0 + dy;
                    bool valid = (xi >= 0) & (xi < W) & (yi >= 0) & (yi < H);
                    float wt = (dx ? tx : 1.f - tx) * (dy ? ty : 1.f - ty);
                    float wv = valid ? wp * wt : 0.f;
                    int iv = valid ? (S + yi * W + xi) * HD : 0;
                    smp[h][dy * 2 + dx][p] = make_float2(wv, __int_as_float(iv));
                }
        }
    }
    __syncwarp();

    int g = lane >> 3, c8 = lane & 7;
    const __half* vb = g_vh + (size_t)(b * NH + h) * (LTOT * HD) + c8 * 4;

    float4 a = make_float4(0.f, 0.f, 0.f, 0.f);
#pragma unroll
    for (int p = 0; p < NPTS; p++) {
        float2 wi = smp[h][g][p];
        int idx = __float_as_int(wi.y);
        uint2 u = *reinterpret_cast<const uint2*>(&vb[idx]);
        float2 f0 = __half22float2(*reinterpret_cast<__half2*>(&u.x));
        float2 f1 = __half22float2(*reinterpret_cast<__half2*>(&u.y));
        a.x = fmaf(wi.x, f0.x, a.x);
        a.y = fmaf(wi.x, f0.y, a.y);
        a.z = fmaf(wi.x, f1.x, a.z);
        a.w = fmaf(wi.x, f1.y, a.w);
    }
#pragma unroll
    for (int s = 8; s <= 16; s <<= 1) {
        a.x += __shfl_xor_sync(0xffffffffu, a.x, s);
        a.y += __shfl_xor_sync(0xffffffffu, a.y, s);
        a.z += __shfl_xor_sync(0xffffffffu, a.z, s);
        a.w += __shfl_xor_sync(0xffffffffu, a.w, s);
    }
    if (lane < 8) {
        __half2* op = reinterpret_cast<__half2*>(&out[(size_t)bq * EMBED + h * HD + lane * 4]);
        op[0] = __floats2half2_rn(a.x, a.y);
        op[1] = __floats2half2_rn(a.z, a.w);
    }
}

extern "C" void kernel_launch(void* const* d_in, const int* in_sizes, int n_in,
                              void* d_out, int out_size) {
    const float* query = (const float*)d_in[0];
    const float* ref_l = (const float*)d_in[1];
    const float* ref_r = (const float*)d_in[2];
    const float* value = (const float*)d_in[3];
    const float* W_off  = (const float*)d_in[6];
    const float* b_off  = (const float*)d_in[7];
    const float* W_attn = (const float*)d_in[8];
    const float* b_attn = (const float*)d_in[9];
    const float* W_val  = (const float*)d_in[10];
    const float* b_val  = (const float*)d_in[11];
    const float* W_out  = (const float*)d_in[12];
    const float* b_out  = (const float*)d_in[13];
    float* out = (float*)d_out;

    float *goffaw, *gbc;
    __half *gvh, *gvalh, *gqh, *gtmph, *gWch, *gWvh, *gWoh;
    cudaGetSymbolAddress((void**)&gvh, g_vh);
    cudaGetSymbolAddress((void**)&goffaw, g_offaw);
    cudaGetSymbolAddress((void**)&gbc, g_bc);
    cudaGetSymbolAddress((void**)&gvalh, g_valh);
    cudaGetSymbolAddress((void**)&gqh, g_qh);
    cudaGetSymbolAddress((void**)&gtmph, g_tmph);
    cudaGetSymbolAddress((void**)&gWch, g_Wch);
    cudaGetSymbolAddress((void**)&gWvh, g_Wvh);
    cudaGetSymbolAddress((void**)&gWoh, g_Woh);

    cudaFuncSetAttribute(gemm_h<1>, cudaFuncAttributeMaxDynamicSharedMemorySize, GEMM_SMEM);
    cudaFuncSetAttribute(gemm_h<0>, cudaFuncAttributeMaxDynamicSharedMemorySize, GEMM_SMEM);

    prep_weights<<<(EMBED * 2 * EMBED + 255) / 256, 256>>>(W_off, b_off, W_attn, b_attn, W_val, W_out);
    f32_to_f16<<<(MV * EMBED * 2 / 4 + 255) / 256, 256>>>(value, gvalh, MV * EMBED * 2 / 4);
    f32_to_f16<<<(MQ * EMBED / 4 + 255) / 256, 256>>>(query, gqh, MQ * EMBED / 4);

    // 1. value projection -> g_vh (fp16 scatter)
    {
        dim3 grid(EMBED / BN, (MV + BM - 1) / BM);
        gemm_h<1><<<grid, 256, GEMM_SMEM>>>(gvalh, gWvh, b_val, gvh, MV, EMBED, EMBED * 2);
    }
    // 2. fused offsets+logits
    {
        dim3 grid((NQK + BN - 1) / BN, (MQ + BM - 1) / BM);
        gemm_h<0><<<grid, 256, GEMM_SMEM>>>(gqh, gWch, gbc, goffaw, MQ, NQK, EMBED);
    }
    // 3. deformable sampling (+fused softmax), fp16 in/out
    sample_kernel<<<MQ, NH * 32>>>(ref_l, ref_r, goffaw, gtmph);
    // 4. output projection -> d_out (fp32)
    {
        dim3 grid(EMBED / BN, (MQ + BM - 1) / BM);
        gemm_h<0><<<grid, 256, GEMM_SMEM>>>(gtmph, gWoh, b_out, out, MQ, EMBED, EMBED);
    }
}

// round 11
// speedup vs baseline: 3.8727x; 1.0196x over previous
#include <cuda_runtime.h>
#include <cuda_fp16.h>
#include <cstdint>
#include <math.h>

#define EMBED 256
#define NH 8
#define NL 3
#define NP 4
#define HD 32
#define P2 8
#define B_ 4
#define NQ 300
#define NK 17
#define LQ (NQ * NK)        // 5100
#define LTOT 13125
#define MQ (B_ * LQ)        // 20400
#define MV (B_ * LTOT)      // 52500
#define NQK 480
#define NPTS (NL * P2)      // 24

__constant__ int c_lvlH[NL] = {100, 50, 25};
__constant__ int c_lvlW[NL] = {100, 50, 25};
__constant__ int c_lvlS[NL] = {0, 10000, 12500};

__device__ __half g_vh[B_ * NH * LTOT * HD];  // [b][h][pix][d] fp16 (26.9 MB)
__device__ float  g_offaw[MQ * NQK];
__device__ float  g_tmp[MQ * EMBED];          // fp32 sampled output
__device__ __half g_Wch[NQK * EMBED];
__device__ float  g_bc[NQK];
__device__ __half g_Wvh[EMBED * 2 * EMBED];
__device__ __half g_Woh[EMBED * EMBED];

__device__ __forceinline__ void cpa16_s(uint32_t s, const void* g, bool pred) {
    int sz = pred ? 16 : 0;
    asm volatile("cp.async.cg.shared.global [%0], [%1], 16, %2;\n" :: "r"(s), "l"(g), "r"(sz));
}

__device__ __forceinline__ void ldm4(uint32_t r[4], uint32_t addr) {
    asm volatile("ldmatrix.sync.aligned.m8n8.x4.shared.b16 {%0,%1,%2,%3}, [%4];"
                 : "=r"(r[0]), "=r"(r[1]), "=r"(r[2]), "=r"(r[3]) : "r"(addr));
}

__device__ __forceinline__ void mma16816(float c[4], const uint32_t a[4], uint32_t b0, uint32_t b1) {
    asm volatile("mma.sync.aligned.m16n8k16.row.col.f32.f16.f16.f32 "
                 "{%0,%1,%2,%3}, {%4,%5,%6,%7}, {%8,%9}, {%0,%1,%2,%3};"
                 : "+f"(c[0]), "+f"(c[1]), "+f"(c[2]), "+f"(c[3])
                 : "r"(a[0]), "r"(a[1]), "r"(a[2]), "r"(a[3]), "r"(b0), "r"(b1));
}

// ---------------------------------------------------------------------------
// fp32-A fp16-B GEMM: C[M,N] = A[M,K] @ B[N,K]^T + bias[N]
// A loaded fp32 via cp.async, converted to fp16 in smem each K-iter.
// BM=128, BN=256, BKH=64; 512 threads, 16 warps (4m x 4n), warp tile 32x64.
// A32 double-buffered, B 3-stage ring. MODE 0: fp32 row-major out.
// MODE 1: fp16 scatter to g_vh layout [b][h][pix][d].
// ---------------------------------------------------------------------------
#define BM 128
#define BN 256
#define BKH 64
#define A32_ROW 272                   // 68 f32
#define A32_BUF (BM * A32_ROW)        // 34816
#define A16_ROW 144                   // 72 halfs
#define A16_BUF (BM * A16_ROW)        // 18432
#define B_ROW 144
#define B_BUF (BN * B_ROW)            // 36864
#define OFF_A16 (2 * A32_BUF)         // 69632
#define OFF_B (OFF_A16 + A16_BUF)     // 88064
#define GEMM_SMEM (OFF_B + 3 * B_BUF) // 198656

template <int MODE>
__global__ void __launch_bounds__(512, 1)
gemm_f(const float* __restrict__ A, const __half* __restrict__ Bm,
       const float* __restrict__ bias, void* __restrict__ Cv,
       int M, int N, int K) {
    extern __shared__ char smem[];
    uint32_t sbase;
    asm("{ .reg .u64 t; cvta.to.shared.u64 t, %1; cvt.u32.u64 %0, t; }"
        : "=r"(sbase) : "l"(smem));

    int tid = threadIdx.x;
    int warp = tid >> 5, lane = tid & 31;
    int wr = warp >> 2, wc = warp & 3;
    int bm = blockIdx.y * BM, bn = blockIdx.x * BN;

    int j8 = lane >> 3, rr = lane & 7;
    int rowx = rr + ((j8 & 1) << 3);
    int colx = (j8 >> 1) << 3;

    float acc[2][8][4];
#pragma unroll
    for (int i = 0; i < 2; i++)
#pragma unroll
        for (int n = 0; n < 8; n++)
#pragma unroll
            for (int t = 0; t < 4; t++) acc[i][n][t] = 0.f;

    int niter = K / BKH;

    auto loadAB = [&](int i) {
        uint32_t a32 = sbase + (i & 1) * A32_BUF;
        uint32_t bb = sbase + OFF_B + (i % 3) * B_BUF;
        int k0 = i * BKH;
#pragma unroll
        for (int j = 0; j < 4; j++) {          // A: 128 rows x 16 chunks(4 f32)
            int c = tid + 512 * j;
            int row = c >> 4, q = c & 15;
            int gr = bm + row;
            bool p = gr < M;
            cpa16_s(a32 + row * A32_ROW + q * 16, &A[(size_t)(p ? gr : 0) * K + k0 + q * 4], p);
        }
#pragma unroll
        for (int j = 0; j < 4; j++) {          // B: 256 rows x 8 chunks(8 halfs)
            int c = tid + 512 * j;
            int row = c >> 3, q = c & 7;
            int gc = bn + row;
            bool p = gc < N;
            cpa16_s(bb + row * B_ROW + q * 16, &Bm[(size_t)(p ? gc : 0) * K + k0 + q * 8], p);
        }
        asm volatile("cp.async.commit_group;\n");
    };

    loadAB(0);
    if (niter > 1) loadAB(1);

    for (int i = 0; i < niter; i++) {
        if (i + 1 < niter) asm volatile("cp.async.wait_group 1;\n" ::: "memory");
        else               asm volatile("cp.async.wait_group 0;\n" ::: "memory");
        __syncthreads();

        // convert A32(stage i&1) -> A16 (single buffer; guarded by top sync)
        {
            uint32_t a32 = sbase + (i & 1) * A32_BUF;
            uint32_t a16 = sbase + OFF_A16;
#pragma unroll
            for (int j = 0; j < 4; j++) {
                int c = tid + 512 * j;
                int row = c >> 4, q = c & 15;
                float4 v;
                asm volatile("ld.shared.v4.f32 {%0,%1,%2,%3}, [%4];"
                             : "=f"(v.x), "=f"(v.y), "=f"(v.z), "=f"(v.w)
                             : "r"(a32 + row * A32_ROW + q * 16));
                __half2 h0 = __floats2half2_rn(v.x, v.y);
                __half2 h1 = __floats2half2_rn(v.z, v.w);
                asm volatile("st.shared.v2.b32 [%0], {%1,%2};"
                             :: "r"(a16 + row * A16_ROW + q * 8),
                                "r"(*(uint32_t*)&h0), "r"(*(uint32_t*)&h1) : "memory");
            }
        }
        __syncthreads();
        if (i + 2 < niter) loadAB(i + 2);      // A32 buf freed by convert; B stage (i+2)%3 free

        uint32_t a16 = sbase + OFF_A16;
        uint32_t bb = sbase + OFF_B + (i % 3) * B_BUF;
#pragma unroll
        for (int ks = 0; ks < 4; ks++) {
            int kc = ks * 16 + colx;
            uint32_t a[2][4], b[4][4];
#pragma unroll
            for (int mt = 0; mt < 2; mt++)
                ldm4(a[mt], a16 + (wr * 32 + mt * 16 + rowx) * A16_ROW + kc * 2);
#pragma unroll
            for (int np = 0; np < 4; np++)
                ldm4(b[np], bb + (wc * 64 + np * 16 + rowx) * B_ROW + kc * 2);
#pragma unroll
            for (int mt = 0; mt < 2; mt++)
#pragma unroll
                for (int nf = 0; nf < 8; nf++)
                    mma16816(acc[mt][nf], a[mt],
                             b[nf >> 1][nf & 1], b[nf >> 1][2 + (nf & 1)]);
        }
    }

    int r4 = lane >> 2, c2 = (lane & 3) * 2;
#pragma unroll
    for (int mt = 0; mt < 2; mt++)
#pragma unroll
        for (int nf = 0; nf < 8; nf++) {
            int gr0 = bm + wr * 32 + mt * 16 + r4;
            int gc = bn + wc * 64 + nf * 8 + c2;
            if (gc < N) {
                float2 bb = *reinterpret_cast<const float2*>(&bias[gc]);
#pragma unroll
                for (int hh = 0; hh < 2; hh++) {
                    int gr = gr0 + hh * 8;
                    if (gr < M) {
                        float vx = acc[mt][nf][hh * 2 + 0] + bb.x;
                        float vy = acc[mt][nf][hh * 2 + 1] + bb.y;
                        if (MODE == 0) {
                            *reinterpret_cast<float2*>(
                                &((float*)Cv)[(size_t)gr * N + gc]) = make_float2(vx, vy);
                        } else {
                            int b = gr / LTOT, l = gr % LTOT;
                            int h = gc >> 5, d = gc & 31;
                            *reinterpret_cast<__half2*>(
                                &((__half*)Cv)[(((size_t)(b * NH + h)) * LTOT + l) * HD + d]) =
                                __floats2half2_rn(vx, vy);
                        }
                    }
                }
            }
        }
}

// ---------------------------------------------------------------------------
// prep: convert + concat weights to fp16; concat biases (fp32)
// ---------------------------------------------------------------------------
__global__ void prep_weights(const float* __restrict__ W_off, const float* __restrict__ b_off,
                             const float* __restrict__ W_attn, const float* __restrict__ b_attn,
                             const float* __restrict__ W_val, const float* __restrict__ W_out) {
    int i = blockIdx.x * blockDim.x + threadIdx.x;
    if (i < 384 * EMBED) g_Wch[i] = __float2half_rn(W_off[i]);
    else if (i < NQK * EMBED) g_Wch[i] = __float2half_rn(W_attn[i - 384 * EMBED]);
    if (i < EMBED * 2 * EMBED) g_Wvh[i] = __float2half_rn(W_val[i]);
    if (i < EMBED * EMBED) g_Woh[i] = __float2half_rn(W_out[i]);
    if (i < 384) g_bc[i] = b_off[i];
    else if (i < NQK) g_bc[i] = b_attn[i - 384];
}

// ---------------------------------------------------------------------------
// Sampling: fp16 gathers; fp32 output (W_out GEMM converts on load).
// ---------------------------------------------------------------------------
#define PPAD 26
__global__ void __launch_bounds__(NH * 32)
sample_kernel(const float* __restrict__ ref_l, const float* __restrict__ ref_r,
              const float* __restrict__ offaw, float* __restrict__ out) {
    __shared__ float2 smp[NH][4][PPAD];

    int bq = blockIdx.x;
    int b = bq / LQ, q = bq % LQ;
    int h = threadIdx.x >> 5;
    int lane = threadIdx.x & 31;
    int nqi = q / NK, nki = q % NK;

    const float* rowp = offaw + (size_t)bq * NQK;
    const float* offp = rowp + h * (NL * NP * 4);
    const float* logp = rowp + 384 + h * (NL * NP);

    float logit = (lane < 12) ? __ldg(&logp[lane]) : -1e30f;
    float m = logit;
#pragma unroll
    for (int s = 16; s; s >>= 1) m = fmaxf(m, __shfl_xor_sync(0xffffffffu, m, s));
    float e = (lane < 12) ? __expf(logit - m) : 0.f;
    float ssum = e;
#pragma unroll
    for (int s = 16; s; s >>= 1) ssum += __shfl_xor_sync(0xffffffffu, ssum, s);
    float ws = e / ssum;

    {
        int p = lane;
        int pl = (p < NPTS) ? p : 0;
        int l = pl >> 3;
        int pr = pl & 7;
        int pp = pr & 3;
        int right = pr >> 2;

        float wp = __shfl_sync(0xffffffffu, ws, l * NP + pp);

        int W = c_lvlW[l], H = c_lvlH[l], S = c_lvlS[l];
        float fW = (float)W, fH = (float)H;

        int rbase = (((b * NQ + nqi) * NL + l) * NK + nki) * 2;
        const float* refp = right ? ref_r : ref_l;
        float rx = __ldg(&refp[rbase]);
        float ry = __ldg(&refp[rbase + 1]);
        int sb = (l * NP + pp) * 4 + right * 2;
        float ox = __ldg(&offp[sb]);
        float oy = __ldg(&offp[sb + 1]);

        float x = fmaf(rx, fW, ox) - 0.5f;
        float y = fmaf(ry, fH, oy) - 0.5f;
        float x0f = floorf(x), y0f = floorf(y);
        int x0 = (int)x0f, y0 = (int)y0f;
        float tx = x - x0f, ty = y - y0f;

        if (p < NPTS) {
#pragma unroll
            for (int dy = 0; dy < 2; dy++)
#pragma unroll
                for (int dx = 0; dx < 2; dx++) {
                    int xi = x0 + dx, yi = y0 + dy;
                    bool valid = (xi >= 0) & (xi < W) & (yi >= 0) & (yi < H);
                    float wt = (dx ? tx : 1.f - tx) * (dy ? ty : 1.f - ty);
                    float wv = valid ? wp * wt : 0.f;
                    int iv = valid ? (S + yi * W + xi) * HD : 0;
                    smp[h][dy * 2 + dx][p] = make_float2(wv, __int_as_float(iv));
                }
        }
    }
    __syncwarp();

    int g = lane >> 3, c8 = lane & 7;
    const __half* vb = g_vh + (size_t)(b * NH + h) * (LTOT * HD) + c8 * 4;

    float4 a = make_float4(0.f, 0.f, 0.f, 0.f);
#pragma unroll
    for (int p = 0; p < NPTS; p++) {
        float2 wi = smp[h][g][p];
        int idx = __float_as_int(wi.y);
        uint2 u = *reinterpret_cast<const uint2*>(&vb[idx]);
        float2 f0 = __half22float2(*reinterpret_cast<__half2*>(&u.x));
        float2 f1 = __half22float2(*reinterpret_cast<__half2*>(&u.y));
        a.x = fmaf(wi.x, f0.x, a.x);
        a.y = fmaf(wi.x, f0.y, a.y);
        a.z = fmaf(wi.x, f1.x, a.z);
        a.w = fmaf(wi.x, f1.y, a.w);
    }
#pragma unroll
    for (int s = 8; s <= 16; s <<= 1) {
        a.x += __shfl_xor_sync(0xffffffffu, a.x, s);
        a.y += __shfl_xor_sync(0xffffffffu, a.y, s);
        a.z += __shfl_xor_sync(0xffffffffu, a.z, s);
        a.w += __shfl_xor_sync(0xffffffffu, a.w, s);
    }
    if (lane < 8)
        *reinterpret_cast<float4*>(&out[(size_t)bq * EMBED + h * HD + lane * 4]) = a;
}

extern "C" void kernel_launch(void* const* d_in, const int* in_sizes, int n_in,
                              void* d_out, int out_size) {
    const float* query = (const float*)d_in[0];
    const float* ref_l = (const float*)d_in[1];
    const float* ref_r = (const float*)d_in[2];
    const float* value = (const float*)d_in[3];
    const float* W_off  = (const float*)d_in[6];
    const float* b_off  = (const float*)d_in[7];
    const float* W_attn = (const float*)d_in[8];
    const float* b_attn = (const float*)d_in[9];
    const float* W_val  = (const float*)d_in[10];
    const float* b_val  = (const float*)d_in[11];
    const float* W_out  = (const float*)d_in[12];
    const float* b_out  = (const float*)d_in[13];
    float* out = (float*)d_out;

    float *goffaw, *gtmp, *gbc;
    __half *gvh, *gWch, *gWvh, *gWoh;
    cudaGetSymbolAddress((void**)&gvh, g_vh);
    cudaGetSymbolAddress((void**)&goffaw, g_offaw);
    cudaGetSymbolAddress((void**)&gtmp, g_tmp);
    cudaGetSymbolAddress((void**)&gbc, g_bc);
    cudaGetSymbolAddress((void**)&gWch, g_Wch);
    cudaGetSymbolAddress((void**)&gWvh, g_Wvh);
    cudaGetSymbolAddress((void**)&gWoh, g_Woh);

    cudaFuncSetAttribute(gemm_f<1>, cudaFuncAttributeMaxDynamicSharedMemorySize, GEMM_SMEM);
    cudaFuncSetAttribute(gemm_f<0>, cudaFuncAttributeMaxDynamicSharedMemorySize, GEMM_SMEM);

    prep_weights<<<(EMBED * 2 * EMBED + 255) / 256, 256>>>(W_off, b_off, W_attn, b_attn, W_val, W_out);

    // 1. value projection: fp32 A in, fp16 scatter out
    {
        dim3 grid(1, (MV + BM - 1) / BM);
        gemm_f<1><<<grid, 512, GEMM_SMEM>>>(value, gWvh, b_val, gvh, MV, EMBED, EMBED * 2);
    }
    // 2. fused offsets+logits
    {
        dim3 grid(2, (MQ + BM - 1) / BM);
        gemm_f<0><<<grid, 512, GEMM_SMEM>>>(query, gWch, gbc, goffaw, MQ, NQK, EMBED);
    }
    // 3. deformable sampling (+fused softmax)
    sample_kernel<<<MQ, NH * 32>>>(ref_l, ref_r, goffaw, gtmp);
    // 4. output projection
    {
        dim3 grid(1, (MQ + BM - 1) / BM);
        gemm_f<0><<<grid, 512, GEMM_SMEM>>>(gtmp, gWoh, b_out, out, MQ, EMBED, EMBED);
    }
}